// round 4
// baseline (speedup 1.0000x reference)
#include <cuda_runtime.h>
#include <cuda_bf16.h>
#include <math.h>

// ---------------- problem constants ----------------
#define LL      8192
#define EE      512
#define DD      512
#define DSTATE  16
#define DCONV   4
#define DTRANK  32
#define NGRAPH  16

// ---------------- scratch (static, alloc-free) ----------------
__device__ float g_cat  [(size_t)LL * 3 * EE];   // 48 MB concat(q,kv,ke)
__device__ float g_x    [(size_t)LL * EE];       // 16 MB after GEMM1+leaky
__device__ float g_xz   [(size_t)LL * 2 * DD];   // 32 MB after in_proj
__device__ float g_xc   [(size_t)LL * DD];       // 16 MB after conv+silu
__device__ float g_dbc  [(size_t)LL * 64];       //  2 MB dt|B|C
__device__ float g_delta[(size_t)LL * DD];       // 16 MB softplus(dt proj)
__device__ float g_y    [(size_t)LL * DD];       // 16 MB gated scan output
__device__ int   g_segstart[NGRAPH + 1];

// ---------------- concat(q, k_v, k_e) ----------------
__global__ void concat3_kernel(const float* __restrict__ q,
                               const float* __restrict__ kv,
                               const float* __restrict__ ke,
                               float* __restrict__ cat) {
    int idx = blockIdx.x * blockDim.x + threadIdx.x;      // over L*384 float4
    if (idx >= LL * 384) return;
    int l  = idx / 384;
    int j4 = idx % 384;
    float4 v;
    if (j4 < 128)       v = ((const float4*)q )[(size_t)l * 128 + j4];
    else if (j4 < 256)  v = ((const float4*)kv)[(size_t)l * 128 + (j4 - 128)];
    else                v = ((const float4*)ke)[(size_t)l * 128 + (j4 - 256)];
    ((float4*)cat)[idx] = v;
}

// ---------------- generic SIMT GEMM: C = epi(A[M,K] @ W[N,K]^T) ----------------
// EPI: 0 = plain store, 1 = bias+leakyrelu, 2 = bias+softplus, 3 = atomic segsum
template <int BM, int BN, int BK, int TM, int TN, int EPI>
__global__ void __launch_bounds__((BM / TM) * (BN / TN))
gemm_wt_kernel(const float* __restrict__ A, int lda,
               const float* __restrict__ W,                 // [N,K] row-major
               const float* __restrict__ bias,
               float* __restrict__ C, int ldc,
               int M, int N, int K,
               const int* __restrict__ index,
               float* __restrict__ segout) {
    constexpr int THREADS = (BM / TM) * (BN / TN);
    constexpr int LA = BM * BK / (4 * THREADS);
    constexpr int LB = BN * BK / (4 * THREADS);
    __shared__ float As[BK][BM];
    __shared__ float Bs[BK][BN];

    const int tid = threadIdx.x;
    const int m0 = blockIdx.y * BM;
    const int n0 = blockIdx.x * BN;
    const int tx = tid % (BN / TN);
    const int ty = tid / (BN / TN);

    float acc[TM][TN];
#pragma unroll
    for (int i = 0; i < TM; i++)
#pragma unroll
        for (int j = 0; j < TN; j++) acc[i][j] = 0.f;

    for (int k0 = 0; k0 < K; k0 += BK) {
#pragma unroll
        for (int i = 0; i < LA; i++) {
            int idx = tid + i * THREADS;
            int row = idx / (BK / 4);
            int kc  = (idx % (BK / 4)) * 4;
            float4 v = *(const float4*)(A + (size_t)(m0 + row) * lda + k0 + kc);
            As[kc + 0][row] = v.x; As[kc + 1][row] = v.y;
            As[kc + 2][row] = v.z; As[kc + 3][row] = v.w;
        }
#pragma unroll
        for (int i = 0; i < LB; i++) {
            int idx = tid + i * THREADS;
            int row = idx / (BK / 4);
            int kc  = (idx % (BK / 4)) * 4;
            float4 v = *(const float4*)(W + (size_t)(n0 + row) * K + k0 + kc);
            Bs[kc + 0][row] = v.x; Bs[kc + 1][row] = v.y;
            Bs[kc + 2][row] = v.z; Bs[kc + 3][row] = v.w;
        }
        __syncthreads();
#pragma unroll
        for (int k = 0; k < BK; k++) {
            float a[TM], b[TN];
#pragma unroll
            for (int i = 0; i < TM; i++) a[i] = As[k][ty * TM + i];
#pragma unroll
            for (int j = 0; j < TN; j++) b[j] = Bs[k][tx * TN + j];
#pragma unroll
            for (int i = 0; i < TM; i++)
#pragma unroll
                for (int j = 0; j < TN; j++) acc[i][j] += a[i] * b[j];
        }
        __syncthreads();
    }

#pragma unroll
    for (int i = 0; i < TM; i++) {
        const int m = m0 + ty * TM + i;
        int node = 0;
        if (EPI == 3) node = index[m];
#pragma unroll
        for (int j = 0; j < TN; j++) {
            const int n = n0 + tx * TN + j;
            float v = acc[i][j];
            if (EPI == 1) {
                v += bias[n];
                v = (v >= 0.f) ? v : 0.01f * v;
            } else if (EPI == 2) {
                v += bias[n];
                v = (v > 20.f) ? v : log1pf(__expf(v));
            }
            if (EPI == 3) {
                atomicAdd(segout + (size_t)node * ldc + n, v);
            } else {
                C[(size_t)m * ldc + n] = v;
            }
        }
    }
}

// ---------------- segmented causal conv (DCONV=4) + SiLU ----------------
__global__ void conv_silu_kernel(const float* __restrict__ xz,   // [L, 2D], x_in = cols [0,512)
                                 const int*   __restrict__ eb,
                                 const float* __restrict__ conv_w, // [D, 4]
                                 const float* __restrict__ conv_b,
                                 float* __restrict__ xc) {
    int idx = blockIdx.x * blockDim.x + threadIdx.x;  // over L*D
    if (idx >= LL * DD) return;
    int l = idx >> 9;
    int c = idx & 511;
    int ebl = eb[l];
    float acc = conv_b[c];
#pragma unroll
    for (int k = 0; k < DCONV; k++) {
        int ls = l + k - (DCONV - 1);
        if (ls >= 0 && eb[ls] == ebl)
            acc += conv_w[c * DCONV + k] * xz[(size_t)ls * (2 * DD) + c];
    }
    float sig = 1.f / (1.f + __expf(-acc));
    xc[idx] = acc * sig;
}

// ---------------- segment boundaries from sorted edge_batch ----------------
__global__ void segstart_kernel(const int* __restrict__ eb) {
    int g = threadIdx.x;
    if (g > NGRAPH) return;
    int lo = 0, hi = LL;
    while (lo < hi) {
        int mid = (lo + hi) >> 1;
        if (eb[mid] < g) lo = mid + 1; else hi = mid;
    }
    g_segstart[g] = lo;
}

// ---------------- segmented selective scan + gating ----------------
// grid (NGRAPH, D/128), block 128. One thread = one channel of one segment.
__global__ void scan_kernel(const float* __restrict__ delta,
                            const float* __restrict__ dbc,   // B at +32, C at +48
                            const float* __restrict__ xc,
                            const float* __restrict__ xz,    // z = cols [512,1024)
                            const float* __restrict__ A_log, // [D, 16]
                            const float* __restrict__ Dvec,
                            float* __restrict__ y) {
    const int c = blockIdx.y * blockDim.x + threadIdx.x;     // 0..511
    const int g = blockIdx.x;
    const int s0 = g_segstart[g];
    const int s1 = g_segstart[g + 1];

    float Acoef[DSTATE];
#pragma unroll
    for (int s = 0; s < DSTATE; s++) Acoef[s] = -__expf(A_log[c * DSTATE + s]);
    const float Dc = Dvec[c];

    float h[DSTATE];
#pragma unroll
    for (int s = 0; s < DSTATE; s++) h[s] = 0.f;

    for (int l = s0; l < s1; l++) {
        const float dlt = delta[(size_t)l * DD + c];
        const float xcv = xc[(size_t)l * DD + c];
        const float zv  = xz[(size_t)l * (2 * DD) + DD + c];
        const float4* bc = (const float4*)(dbc + (size_t)l * 64 + DTRANK);
        const float dx = dlt * xcv;
        float yv = 0.f;
#pragma unroll
        for (int q4 = 0; q4 < 4; q4++) {
            float4 B4 = __ldg(bc + q4);
            float4 C4 = __ldg(bc + 4 + q4);
            float bb[4] = {B4.x, B4.y, B4.z, B4.w};
            float cc[4] = {C4.x, C4.y, C4.z, C4.w};
#pragma unroll
            for (int j = 0; j < 4; j++) {
                int s = q4 * 4 + j;
                float dA = __expf(dlt * Acoef[s]);
                h[s] = dA * h[s] + dx * bb[j];
                yv += h[s] * cc[j];
            }
        }
        const float sig = 1.f / (1.f + __expf(-zv));
        y[(size_t)l * DD + c] = (yv + Dc * xcv) * (zv * sig);
    }
}

// ---------------- zero output ----------------
__global__ void zero_kernel(float* __restrict__ p, int n4) {
    int idx = blockIdx.x * blockDim.x + threadIdx.x;
    if (idx < n4) ((float4*)p)[idx] = make_float4(0.f, 0.f, 0.f, 0.f);
}

// ---------------- host launcher ----------------
extern "C" void kernel_launch(void* const* d_in, const int* in_sizes, int n_in,
                              void* d_out, int out_size) {
    const float* q   = (const float*)d_in[0];
    const float* k_v = (const float*)d_in[1];
    const float* k_e = (const float*)d_in[2];
    const int*   index = (const int*)d_in[3];
    // nnode may or may not be materialized as a size-1 input
    int base = (in_sizes[4] == 1) ? 5 : 4;
    const int*   edge_batch = (const int*)d_in[base + 0];
    const float* w_weight   = (const float*)d_in[base + 1];
    const float* w_bias     = (const float*)d_in[base + 2];
    const float* in_proj_w  = (const float*)d_in[base + 3];
    const float* conv_w     = (const float*)d_in[base + 4];
    const float* conv_b     = (const float*)d_in[base + 5];
    const float* x_proj_w   = (const float*)d_in[base + 6];
    const float* dt_proj_w  = (const float*)d_in[base + 7];
    const float* dt_proj_b  = (const float*)d_in[base + 8];
    const float* A_log      = (const float*)d_in[base + 9];
    const float* Dvec       = (const float*)d_in[base + 10];
    const float* out_proj_w = (const float*)d_in[base + 11];
    float* out = (float*)d_out;

    void *p_cat, *p_x, *p_xz, *p_xc, *p_dbc, *p_delta, *p_y;
    cudaGetSymbolAddress(&p_cat,   g_cat);
    cudaGetSymbolAddress(&p_x,     g_x);
    cudaGetSymbolAddress(&p_xz,    g_xz);
    cudaGetSymbolAddress(&p_xc,    g_xc);
    cudaGetSymbolAddress(&p_dbc,   g_dbc);
    cudaGetSymbolAddress(&p_delta, g_delta);
    cudaGetSymbolAddress(&p_y,     g_y);
    float* cat   = (float*)p_cat;
    float* x     = (float*)p_x;
    float* xz    = (float*)p_xz;
    float* xc    = (float*)p_xc;
    float* dbc   = (float*)p_dbc;
    float* delta = (float*)p_delta;
    float* y     = (float*)p_y;

    // 1. concat(q, k_v, k_e) -> cat [L, 1536]
    concat3_kernel<<<(LL * 384 + 255) / 256, 256>>>(q, k_v, k_e, cat);

    // 2. x = leakyrelu(cat @ w_weight^T + w_bias)  [L, 512], K=1536
    gemm_wt_kernel<128, 64, 16, 8, 4, 1><<<dim3(EE / 64, LL / 128), 256>>>(
        cat, 3 * EE, w_weight, w_bias, x, EE, LL, EE, 3 * EE, nullptr, nullptr);

    // 3. xz = x @ in_proj_w^T  [L, 1024], K=512
    gemm_wt_kernel<128, 64, 16, 8, 4, 0><<<dim3(2 * DD / 64, LL / 128), 256>>>(
        x, EE, in_proj_w, nullptr, xz, 2 * DD, LL, 2 * DD, EE, nullptr, nullptr);

    // 4. xc = silu(segmented_conv4(xz[:, :512]))
    conv_silu_kernel<<<(LL * DD + 255) / 256, 256>>>(xz, edge_batch, conv_w, conv_b, xc);

    // 5. dbc = xc @ x_proj_w^T  [L, 64], K=512
    gemm_wt_kernel<128, 64, 16, 8, 4, 0><<<dim3(1, LL / 128), 256>>>(
        xc, DD, x_proj_w, nullptr, dbc, 64, LL, 64, DD, nullptr, nullptr);

    // 6. delta = softplus(dbc[:, :32] @ dt_proj_w^T + dt_proj_b)  [L, 512], K=32
    gemm_wt_kernel<128, 64, 16, 8, 4, 2><<<dim3(DD / 64, LL / 128), 256>>>(
        dbc, 64, dt_proj_w, dt_proj_b, delta, DD, LL, DD, DTRANK, nullptr, nullptr);

    // 7. segment boundaries
    segstart_kernel<<<1, 32>>>(edge_batch);

    // 8. segmented selective scan + D skip + z gating -> y [L, 512]
    scan_kernel<<<dim3(NGRAPH, DD / 128), 128>>>(delta, dbc, xc, xz, A_log, Dvec, y);

    // 9. zero output
    zero_kernel<<<(out_size / 4 + 255) / 256, 256>>>(out, out_size / 4);

    // 10. out[node] += y @ out_proj_w^T  (fused atomic segment-sum)
    gemm_wt_kernel<128, 64, 16, 8, 4, 3><<<dim3(EE / 64, LL / 128), 256>>>(
        y, DD, out_proj_w, nullptr, nullptr, EE, LL, EE, DD, index, out);
}

// round 6
// speedup vs baseline: 1.7282x; 1.7282x over previous
#include <cuda_runtime.h>
#include <cuda_bf16.h>
#include <math.h>
#include <stdint.h>

// ---------------- problem constants ----------------
#define LL      8192
#define EE      512
#define DD      512
#define DSTATE  16
#define DCONV   4
#define DTRANK  32
#define NGRAPH  16

// tcgen05 is an arch-accelerated feature: only legal in sm_103a/sm_100a passes.
// A plain compute_103 PTX pass must not see any tcgen05/TMEM instruction.
#if defined(__CUDA_ARCH_FEAT_SM103_ALL) || defined(__CUDA_ARCH_FEAT_SM100_ALL) || defined(__CUDA_ARCH_FEAT_SM101_ALL)
#define HAS_TCGEN05 1
#else
#define HAS_TCGEN05 0
#endif

// ---------------- scratch (static, alloc-free) ----------------
__device__ __nv_bfloat16 g_cat_hi[(size_t)LL * 3 * EE];
__device__ __nv_bfloat16 g_cat_lo[(size_t)LL * 3 * EE];
__device__ __nv_bfloat16 g_x_hi  [(size_t)LL * EE];
__device__ __nv_bfloat16 g_x_lo  [(size_t)LL * EE];
__device__ __nv_bfloat16 g_y_hi  [(size_t)LL * DD];
__device__ __nv_bfloat16 g_y_lo  [(size_t)LL * DD];
__device__ __nv_bfloat16 g_wW_hi [(size_t)EE * 3 * EE];
__device__ __nv_bfloat16 g_wW_lo [(size_t)EE * 3 * EE];
__device__ __nv_bfloat16 g_wI_hi [(size_t)2 * DD * EE];
__device__ __nv_bfloat16 g_wI_lo [(size_t)2 * DD * EE];
__device__ __nv_bfloat16 g_wO_hi [(size_t)EE * DD];
__device__ __nv_bfloat16 g_wO_lo [(size_t)EE * DD];
__device__ float g_xz   [(size_t)LL * 2 * DD];
__device__ float g_xc   [(size_t)LL * DD];
__device__ float g_dbc  [(size_t)LL * 64];
__device__ float g_delta[(size_t)LL * DD];
__device__ int   g_segstart[NGRAPH + 1];

// ================= PTX helpers (guarded; sm_103a tcgen05) =================
#if HAS_TCGEN05
__device__ __forceinline__ uint32_t smem_u32(const void* p) {
    uint32_t a;
    asm("{ .reg .u64 t; cvta.to.shared.u64 t, %1; cvt.u32.u64 %0, t; }"
        : "=r"(a) : "l"(p));
    return a;
}
__device__ __forceinline__ uint32_t elect_one_pred() {
    uint32_t pred;
    asm volatile("{\n\t.reg .pred p;\n\telect.sync _|p, 0xFFFFFFFF;\n\t"
                 "selp.b32 %0, 1, 0, p;\n\t}" : "=r"(pred));
    return pred;
}
#define TCGEN05_ALLOC(sm_addr, nCols) \
    asm volatile("tcgen05.alloc.cta_group::1.sync.aligned.shared::cta.b32 [%0], %1;" \
                 :: "r"((uint32_t)(sm_addr)), "r"((uint32_t)(nCols)) : "memory")
#define TCGEN05_DEALLOC(tmem_addr, nCols) \
    asm volatile("tcgen05.dealloc.cta_group::1.sync.aligned.b32 %0, %1;" \
                 :: "r"(tmem_addr), "r"((uint32_t)(nCols)))
#define TCGEN05_RELINQ() \
    asm volatile("tcgen05.relinquish_alloc_permit.cta_group::1.sync.aligned;")
#define TCGEN05_COMMIT(mbar) \
    asm volatile("tcgen05.commit.cta_group::1.mbarrier::arrive::one.shared::cluster.b64 [%0];" \
                 :: "r"((uint32_t)(mbar)) : "memory")
#define TCGEN05_FENCE_AFTER() \
    asm volatile("tcgen05.fence::after_thread_sync;" ::: "memory")
#define TCGEN05_WAIT_LD() \
    asm volatile("tcgen05.wait::ld.sync.aligned;" ::: "memory")
#define FENCE_ASYNC_SHARED() \
    asm volatile("fence.proxy.async.shared::cta;" ::: "memory")
#define MBARRIER_INIT(mbar, cnt) \
    asm volatile("mbarrier.init.shared.b64 [%0], %1;" \
                 :: "r"((uint32_t)(mbar)), "r"((uint32_t)(cnt)) : "memory")
#define MBARRIER_WAIT_PARITY(mbar, parity) do { \
    uint32_t _mbar = (uint32_t)(mbar); \
    uint32_t _par  = (uint32_t)(parity); \
    uint32_t _done; \
    asm volatile("{\n\t.reg .pred p;\n\t" \
        "mbarrier.try_wait.parity.acquire.cta.shared::cta.b64 p, [%1], %2;\n\t" \
        "selp.b32 %0, 1, 0, p;\n\t}" : "=r"(_done) : "r"(_mbar), "r"(_par) : "memory"); \
    if (!_done) { \
        asm volatile("{\n\t.reg .pred P1;\n\t" \
            "WAIT_LOOP_%=:\n\t" \
            "mbarrier.try_wait.parity.acquire.cta.shared::cta.b64 P1, [%0], %1, 0x989680;\n\t" \
            "@P1 bra.uni WAIT_DONE_%=;\n\t" \
            "bra.uni WAIT_LOOP_%=;\n\t" \
            "WAIT_DONE_%=:\n\t}" :: "r"(_mbar), "r"(_par) : "memory"); \
    } \
} while (0)
#define TCGEN05_LD_32X32B_X32(r, tmem_addr) \
    asm volatile("tcgen05.ld.sync.aligned.32x32b.x32.b32 " \
        "{%0, %1, %2, %3, %4, %5, %6, %7, %8, %9, %10, %11, %12, %13, %14, %15, " \
        " %16, %17, %18, %19, %20, %21, %22, %23, %24, %25, %26, %27, %28, %29, %30, %31}, [%32];" \
        : "=r"((r)[0]),  "=r"((r)[1]),  "=r"((r)[2]),  "=r"((r)[3]), \
          "=r"((r)[4]),  "=r"((r)[5]),  "=r"((r)[6]),  "=r"((r)[7]), \
          "=r"((r)[8]),  "=r"((r)[9]),  "=r"((r)[10]), "=r"((r)[11]), \
          "=r"((r)[12]), "=r"((r)[13]), "=r"((r)[14]), "=r"((r)[15]), \
          "=r"((r)[16]), "=r"((r)[17]), "=r"((r)[18]), "=r"((r)[19]), \
          "=r"((r)[20]), "=r"((r)[21]), "=r"((r)[22]), "=r"((r)[23]), \
          "=r"((r)[24]), "=r"((r)[25]), "=r"((r)[26]), "=r"((r)[27]), \
          "=r"((r)[28]), "=r"((r)[29]), "=r"((r)[30]), "=r"((r)[31]) \
        : "r"(tmem_addr))

// bf16 SS-mode MMA, cta_group::1, kind::f16 (bf16 via idesc), fp32 accum
__device__ __forceinline__ void mma_bf16_ss(uint32_t d_tmem, uint64_t a_desc,
                                            uint64_t b_desc, uint32_t idesc,
                                            uint32_t acc) {
    asm volatile("{\n\t.reg .pred p;\n\tsetp.ne.u32 p, %4, 0;\n\t"
        "tcgen05.mma.cta_group::1.kind::f16 [%0], %1, %2, %3, {%5, %5, %5, %5}, p;\n\t}"
        :: "r"(d_tmem), "l"(a_desc), "l"(b_desc), "r"(idesc), "r"(acc), "r"(0u)
        : "memory");
}
__device__ __forceinline__ uint64_t make_desc_sw128(uint32_t addr) {
    const uint64_t BASE = (2ull << 61) | (1ull << 46) | (64ull << 32) | (1ull << 16);
    return BASE | ((uint64_t)(addr >> 4) & 0x3FFF);
}
#endif  // HAS_TCGEN05

#define SWZ(o) ((o) ^ (((o) >> 3) & 0x70))

// ================= split-bf16 GEMM (tcgen05 when available, SIMT otherwise) =
// C[M=128/CTA, N=128/CTA] = (Ahi+Alo)[M,K] @ (Whi+Wlo)[N,K]^T  (lo*lo dropped)
// EPI: 0 = fp32 store | 1 = bias+leakyrelu -> bf16 hi/lo | 3 = atomic segsum
#define TC_SMEM_BYTES (1024 + 2 * 4 * 16384)

#if HAS_TCGEN05
__device__ __forceinline__ void tc_load_tile(char* dst, const __nv_bfloat16* src,
                                             int ld, int tid) {
#pragma unroll
    for (int t = 0; t < 4; t++) {
        int idx = tid + t * 256;          // 0..1023
        int r   = idx >> 3;
        int c16 = idx & 7;
        uint4 v = *(const uint4*)(src + (size_t)r * ld + c16 * 8);
        *(uint4*)(dst + SWZ(r * 128 + c16 * 16)) = v;
    }
}
#endif

template <int EPI>
__global__ void __launch_bounds__(256, 1)
tc_gemm_kernel(const __nv_bfloat16* __restrict__ Ahi,
               const __nv_bfloat16* __restrict__ Alo, int K,
               const __nv_bfloat16* __restrict__ Whi,
               const __nv_bfloat16* __restrict__ Wlo,
               const float* __restrict__ bias,
               float* __restrict__ Cf, int ldc,
               __nv_bfloat16* __restrict__ Chi,
               __nv_bfloat16* __restrict__ Clo, int ldch,
               const int* __restrict__ index,
               float* __restrict__ segout) {
    extern __shared__ char smem[];
    const int tid = threadIdx.x;
    const int n0 = blockIdx.x * 128;
    const int m0 = blockIdx.y * 128;

#if HAS_TCGEN05
    // ======================= tcgen05 path =======================
    const int wid = tid >> 5;
    const int lid = tid & 31;
    const uint32_t sb = smem_u32(smem);

    if (wid == 0) TCGEN05_ALLOC(sb, 128);
    if (tid == 0) { MBARRIER_INIT(sb + 16, 1); MBARRIER_INIT(sb + 24, 1); }
    __syncthreads();
    uint32_t tmem;
    asm volatile("ld.shared.b32 %0, [%1];" : "=r"(tmem) : "r"(sb));

    const int NC = K >> 6;                 // 64-bf16 chunks
    const uint32_t idesc = (1u << 4) | (1u << 7) | (1u << 10) |
                           ((128u / 8) << 17) | ((128u / 16) << 24);

    const __nv_bfloat16* Ahi0 = Ahi + (size_t)m0 * K;
    const __nv_bfloat16* Alo0 = Alo + (size_t)m0 * K;
    const __nv_bfloat16* Whi0 = Whi + (size_t)n0 * K;
    const __nv_bfloat16* Wlo0 = Wlo + (size_t)n0 * K;

    {
        char* base = smem + 1024;
        tc_load_tile(base,          Ahi0, K, tid);
        tc_load_tile(base + 16384,  Alo0, K, tid);
        tc_load_tile(base + 32768,  Whi0, K, tid);
        tc_load_tile(base + 49152,  Wlo0, K, tid);
    }
    FENCE_ASYNC_SHARED();
    __syncthreads();

    int ph0 = 0, ph1 = 0;
    for (int i = 0; i < NC; i++) {
        const int b = i & 1;
        if (wid == 0) {
            if (elect_one_pred()) {
                const uint32_t tb = sb + 1024 + b * 65536;
                const uint64_t dAh = make_desc_sw128(tb);
                const uint64_t dAl = make_desc_sw128(tb + 16384);
                const uint64_t dWh = make_desc_sw128(tb + 32768);
                const uint64_t dWl = make_desc_sw128(tb + 49152);
#pragma unroll
                for (int ks = 0; ks < 4; ks++)
                    mma_bf16_ss(tmem, dAh + ks * 2, dWh + ks * 2, idesc,
                                (i > 0 || ks > 0) ? 1u : 0u);
#pragma unroll
                for (int ks = 0; ks < 4; ks++)
                    mma_bf16_ss(tmem, dAh + ks * 2, dWl + ks * 2, idesc, 1u);
#pragma unroll
                for (int ks = 0; ks < 4; ks++)
                    mma_bf16_ss(tmem, dAl + ks * 2, dWh + ks * 2, idesc, 1u);
                TCGEN05_COMMIT(sb + 16 + b * 8);
            }
        }
        if (i + 1 < NC) {
            const int b2 = b ^ 1;
            if (i >= 1) {   // buffer b2 was read by chunk i-1's MMAs
                if (b2 == 0) { MBARRIER_WAIT_PARITY(sb + 16, ph0 & 1); ph0++; }
                else         { MBARRIER_WAIT_PARITY(sb + 24, ph1 & 1); ph1++; }
            }
            const int k0 = (i + 1) << 6;
            char* base = smem + 1024 + b2 * 65536;
            tc_load_tile(base,          Ahi0 + k0, K, tid);
            tc_load_tile(base + 16384,  Alo0 + k0, K, tid);
            tc_load_tile(base + 32768,  Whi0 + k0, K, tid);
            tc_load_tile(base + 49152,  Wlo0 + k0, K, tid);
            FENCE_ASYNC_SHARED();
            __syncthreads();
        }
    }
    if (((NC - 1) & 1) == 0) { MBARRIER_WAIT_PARITY(sb + 16, ph0 & 1); }
    else                     { MBARRIER_WAIT_PARITY(sb + 24, ph1 & 1); }
    TCGEN05_FENCE_AFTER();

    if (wid < 4) {
        const int m = m0 + wid * 32 + lid;
        int node = 0;
        if (EPI == 3) node = index[m];
#pragma unroll
        for (int cb = 0; cb < 4; cb++) {
            uint32_t dr[32];
            TCGEN05_LD_32X32B_X32(dr, tmem + cb * 32);
            TCGEN05_WAIT_LD();
            const int nb = n0 + cb * 32;
            if (EPI == 0) {
                float4* dst = (float4*)(Cf + (size_t)m * ldc + nb);
#pragma unroll
                for (int j4 = 0; j4 < 8; j4++)
                    dst[j4] = make_float4(__uint_as_float(dr[j4 * 4 + 0]),
                                          __uint_as_float(dr[j4 * 4 + 1]),
                                          __uint_as_float(dr[j4 * 4 + 2]),
                                          __uint_as_float(dr[j4 * 4 + 3]));
            } else if (EPI == 1) {
                __nv_bfloat162 hi[16], lo[16];
#pragma unroll
                for (int j2 = 0; j2 < 16; j2++) {
                    float a = __uint_as_float(dr[j2 * 2 + 0]) + bias[nb + j2 * 2 + 0];
                    float b = __uint_as_float(dr[j2 * 2 + 1]) + bias[nb + j2 * 2 + 1];
                    a = (a >= 0.f) ? a : 0.01f * a;
                    b = (b >= 0.f) ? b : 0.01f * b;
                    __nv_bfloat162 h = __floats2bfloat162_rn(a, b);
                    hi[j2] = h;
                    lo[j2] = __floats2bfloat162_rn(a - __bfloat162float(h.x),
                                                   b - __bfloat162float(h.y));
                }
                uint4* dh = (uint4*)(Chi + (size_t)m * ldch + nb);
                uint4* dl = (uint4*)(Clo + (size_t)m * ldch + nb);
#pragma unroll
                for (int j4 = 0; j4 < 4; j4++) {
                    dh[j4] = ((uint4*)hi)[j4];
                    dl[j4] = ((uint4*)lo)[j4];
                }
            } else {
                float* dst = segout + (size_t)node * ldc + nb;
#pragma unroll
                for (int j = 0; j < 32; j++)
                    atomicAdd(dst + j, __uint_as_float(dr[j]));
            }
        }
    }
    __syncthreads();
    if (wid == 0) {
        TCGEN05_RELINQ();
        TCGEN05_DEALLOC(tmem, 128);
    }
#else
    // ======================= SIMT fallback (non-'a' pass) =======================
    float* As = (float*)smem;           // [16][128]
    float* Bs = As + 16 * 128;          // [16][128]
    const int tx = tid & 15;            // n / 8
    const int ty = tid >> 4;            // m / 8

    float acc[8][8];
#pragma unroll
    for (int i = 0; i < 8; i++)
#pragma unroll
        for (int j = 0; j < 8; j++) acc[i][j] = 0.f;

    const __nv_bfloat16* Ahi0 = Ahi + (size_t)m0 * K;
    const __nv_bfloat16* Alo0 = Alo + (size_t)m0 * K;
    const __nv_bfloat16* Whi0 = Whi + (size_t)n0 * K;
    const __nv_bfloat16* Wlo0 = Wlo + (size_t)n0 * K;

    const int lrow = tid >> 1;
    const int lkc  = (tid & 1) * 8;

    for (int k0 = 0; k0 < K; k0 += 16) {
        {
            uint4 vh = *(const uint4*)(Ahi0 + (size_t)lrow * K + k0 + lkc);
            uint4 vl = *(const uint4*)(Alo0 + (size_t)lrow * K + k0 + lkc);
            const __nv_bfloat16* hh = (const __nv_bfloat16*)&vh;
            const __nv_bfloat16* ll = (const __nv_bfloat16*)&vl;
#pragma unroll
            for (int j = 0; j < 8; j++)
                As[(lkc + j) * 128 + lrow] =
                    __bfloat162float(hh[j]) + __bfloat162float(ll[j]);
        }
        {
            uint4 vh = *(const uint4*)(Whi0 + (size_t)lrow * K + k0 + lkc);
            uint4 vl = *(const uint4*)(Wlo0 + (size_t)lrow * K + k0 + lkc);
            const __nv_bfloat16* hh = (const __nv_bfloat16*)&vh;
            const __nv_bfloat16* ll = (const __nv_bfloat16*)&vl;
#pragma unroll
            for (int j = 0; j < 8; j++)
                Bs[(lkc + j) * 128 + lrow] =
                    __bfloat162float(hh[j]) + __bfloat162float(ll[j]);
        }
        __syncthreads();
#pragma unroll
        for (int k = 0; k < 16; k++) {
            float a[8], b[8];
#pragma unroll
            for (int i = 0; i < 8; i++) a[i] = As[k * 128 + ty * 8 + i];
#pragma unroll
            for (int j = 0; j < 8; j++) b[j] = Bs[k * 128 + tx * 8 + j];
#pragma unroll
            for (int i = 0; i < 8; i++)
#pragma unroll
                for (int j = 0; j < 8; j++) acc[i][j] += a[i] * b[j];
        }
        __syncthreads();
    }

#pragma unroll
    for (int i = 0; i < 8; i++) {
        const int m = m0 + ty * 8 + i;
        int node = 0;
        if (EPI == 3) node = index[m];
#pragma unroll
        for (int j = 0; j < 8; j++) {
            const int n = n0 + tx * 8 + j;
            float v = acc[i][j];
            if (EPI == 1) {
                v += bias[n];
                v = (v >= 0.f) ? v : 0.01f * v;
                __nv_bfloat16 h = __float2bfloat16(v);
                Chi[(size_t)m * ldch + n] = h;
                Clo[(size_t)m * ldch + n] = __float2bfloat16(v - __bfloat162float(h));
            } else if (EPI == 3) {
                atomicAdd(segout + (size_t)node * ldc + n, v);
            } else {
                Cf[(size_t)m * ldc + n] = v;
            }
        }
    }
#endif
}

// ---------------- split fp32 -> bf16 hi/lo ----------------
__global__ void split_kernel(const float* __restrict__ w,
                             __nv_bfloat16* __restrict__ hi,
                             __nv_bfloat16* __restrict__ lo, int n) {
    int i = blockIdx.x * blockDim.x + threadIdx.x;
    if (i >= n) return;
    float v = w[i];
    __nv_bfloat16 h = __float2bfloat16(v);
    hi[i] = h;
    lo[i] = __float2bfloat16(v - __bfloat162float(h));
}

// ---------------- concat(q, k_v, k_e) + split ----------------
__global__ void concat_split_kernel(const float* __restrict__ q,
                                    const float* __restrict__ kv,
                                    const float* __restrict__ ke,
                                    __nv_bfloat16* __restrict__ hi,
                                    __nv_bfloat16* __restrict__ lo) {
    int idx = blockIdx.x * blockDim.x + threadIdx.x;   // L*384 float4
    if (idx >= LL * 384) return;
    int l  = idx / 384;
    int j4 = idx % 384;
    float4 v;
    if (j4 < 128)       v = ((const float4*)q )[(size_t)l * 128 + j4];
    else if (j4 < 256)  v = ((const float4*)kv)[(size_t)l * 128 + (j4 - 128)];
    else                v = ((const float4*)ke)[(size_t)l * 128 + (j4 - 256)];
    __nv_bfloat162 h0 = __floats2bfloat162_rn(v.x, v.y);
    __nv_bfloat162 h1 = __floats2bfloat162_rn(v.z, v.w);
    __nv_bfloat162 l0 = __floats2bfloat162_rn(v.x - __bfloat162float(h0.x),
                                              v.y - __bfloat162float(h0.y));
    __nv_bfloat162 l1 = __floats2bfloat162_rn(v.z - __bfloat162float(h1.x),
                                              v.w - __bfloat162float(h1.y));
    ((__nv_bfloat162*)hi)[idx * 2 + 0] = h0;
    ((__nv_bfloat162*)hi)[idx * 2 + 1] = h1;
    ((__nv_bfloat162*)lo)[idx * 2 + 0] = l0;
    ((__nv_bfloat162*)lo)[idx * 2 + 1] = l1;
}

// ---------------- SIMT GEMM (small GEMMs): C = epi(A[M,K] @ W[N,K]^T) -------
// EPI: 0 = plain store, 2 = bias+softplus
template <int BM, int BN, int BK, int TM, int TN, int EPI>
__global__ void __launch_bounds__((BM / TM) * (BN / TN))
gemm_wt_kernel(const float* __restrict__ A, int lda,
               const float* __restrict__ W,
               const float* __restrict__ bias,
               float* __restrict__ C, int ldc,
               int M, int N, int K) {
    constexpr int THREADS = (BM / TM) * (BN / TN);
    constexpr int LA = BM * BK / (4 * THREADS);
    constexpr int LB = BN * BK / (4 * THREADS);
    __shared__ float As[BK][BM];
    __shared__ float Bs[BK][BN];

    const int tid = threadIdx.x;
    const int m0 = blockIdx.y * BM;
    const int n0 = blockIdx.x * BN;
    const int tx = tid % (BN / TN);
    const int ty = tid / (BN / TN);

    float acc[TM][TN];
#pragma unroll
    for (int i = 0; i < TM; i++)
#pragma unroll
        for (int j = 0; j < TN; j++) acc[i][j] = 0.f;

    for (int k0 = 0; k0 < K; k0 += BK) {
#pragma unroll
        for (int i = 0; i < LA; i++) {
            int idx = tid + i * THREADS;
            int row = idx / (BK / 4);
            int kc  = (idx % (BK / 4)) * 4;
            float4 v = *(const float4*)(A + (size_t)(m0 + row) * lda + k0 + kc);
            As[kc + 0][row] = v.x; As[kc + 1][row] = v.y;
            As[kc + 2][row] = v.z; As[kc + 3][row] = v.w;
        }
#pragma unroll
        for (int i = 0; i < LB; i++) {
            int idx = tid + i * THREADS;
            int row = idx / (BK / 4);
            int kc  = (idx % (BK / 4)) * 4;
            float4 v = *(const float4*)(W + (size_t)(n0 + row) * K + k0 + kc);
            Bs[kc + 0][row] = v.x; Bs[kc + 1][row] = v.y;
            Bs[kc + 2][row] = v.z; Bs[kc + 3][row] = v.w;
        }
        __syncthreads();
#pragma unroll
        for (int k = 0; k < BK; k++) {
            float a[TM], b[TN];
#pragma unroll
            for (int i = 0; i < TM; i++) a[i] = As[k][ty * TM + i];
#pragma unroll
            for (int j = 0; j < TN; j++) b[j] = Bs[k][tx * TN + j];
#pragma unroll
            for (int i = 0; i < TM; i++)
#pragma unroll
                for (int j = 0; j < TN; j++) acc[i][j] += a[i] * b[j];
        }
        __syncthreads();
    }

#pragma unroll
    for (int i = 0; i < TM; i++) {
        const int m = m0 + ty * TM + i;
#pragma unroll
        for (int j = 0; j < TN; j++) {
            const int n = n0 + tx * TN + j;
            float v = acc[i][j];
            if (EPI == 2) {
                v += bias[n];
                v = (v > 20.f) ? v : log1pf(__expf(v));
            }
            C[(size_t)m * ldc + n] = v;
        }
    }
}

// ---------------- segmented causal conv (DCONV=4) + SiLU, float4 ------------
__global__ void conv_silu_kernel(const float* __restrict__ xz,   // [L, 2D]
                                 const int*   __restrict__ eb,
                                 const float* __restrict__ conv_w, // [D, 4]
                                 const float* __restrict__ conv_b,
                                 float* __restrict__ xc) {
    int idx = blockIdx.x * blockDim.x + threadIdx.x;  // L * 128 float4
    if (idx >= LL * 128) return;
    int l  = idx >> 7;
    int c4 = idx & 127;
    int ebl = eb[l];
    float4 acc = ((const float4*)conv_b)[c4];
    float4 w0 = ((const float4*)conv_w)[c4 * 4 + 0];
    float4 w1 = ((const float4*)conv_w)[c4 * 4 + 1];
    float4 w2 = ((const float4*)conv_w)[c4 * 4 + 2];
    float4 w3 = ((const float4*)conv_w)[c4 * 4 + 3];
    const float* wp0 = (const float*)&w0;
    const float* wp1 = (const float*)&w1;
    const float* wp2 = (const float*)&w2;
    const float* wp3 = (const float*)&w3;
#pragma unroll
    for (int k = 0; k < DCONV; k++) {
        int ls = l + k - (DCONV - 1);
        if (ls >= 0 && eb[ls] == ebl) {
            float4 xv = ((const float4*)xz)[(size_t)ls * 256 + c4];
            acc.x += wp0[k] * xv.x;
            acc.y += wp1[k] * xv.y;
            acc.z += wp2[k] * xv.z;
            acc.w += wp3[k] * xv.w;
        }
    }
    acc.x *= 1.f / (1.f + __expf(-acc.x));
    acc.y *= 1.f / (1.f + __expf(-acc.y));
    acc.z *= 1.f / (1.f + __expf(-acc.z));
    acc.w *= 1.f / (1.f + __expf(-acc.w));
    ((float4*)xc)[idx] = acc;
}

// ---------------- segment boundaries ----------------
__global__ void segstart_kernel(const int* __restrict__ eb) {
    int g = threadIdx.x;
    if (g > NGRAPH) return;
    int lo = 0, hi = LL;
    while (lo < hi) {
        int mid = (lo + hi) >> 1;
        if (eb[mid] < g) lo = mid + 1; else hi = mid;
    }
    g_segstart[g] = lo;
}

// ---------------- segmented selective scan + gating -> bf16 hi/lo -----------
__global__ void scan_kernel(const float* __restrict__ delta,
                            const float* __restrict__ dbc,
                            const float* __restrict__ xc,
                            const float* __restrict__ xz,
                            const float* __restrict__ A_log,
                            const float* __restrict__ Dvec,
                            __nv_bfloat16* __restrict__ y_hi,
                            __nv_bfloat16* __restrict__ y_lo) {
    const int c = blockIdx.y * blockDim.x + threadIdx.x;
    const int g = blockIdx.x;
    const int s0 = g_segstart[g];
    const int s1 = g_segstart[g + 1];

    float Acoef[DSTATE];
#pragma unroll
    for (int s = 0; s < DSTATE; s++) Acoef[s] = -__expf(A_log[c * DSTATE + s]);
    const float Dc = Dvec[c];

    float h[DSTATE];
#pragma unroll
    for (int s = 0; s < DSTATE; s++) h[s] = 0.f;

    for (int l = s0; l < s1; l++) {
        const float dlt = delta[(size_t)l * DD + c];
        const float xcv = xc[(size_t)l * DD + c];
        const float zv  = xz[(size_t)l * (2 * DD) + DD + c];
        const float4* bc = (const float4*)(dbc + (size_t)l * 64 + DTRANK);
        const float dx = dlt * xcv;
        float yv = 0.f;
#pragma unroll
        for (int q4 = 0; q4 < 4; q4++) {
            float4 B4 = __ldg(bc + q4);
            float4 C4 = __ldg(bc + 4 + q4);
            float bb[4] = {B4.x, B4.y, B4.z, B4.w};
            float cc[4] = {C4.x, C4.y, C4.z, C4.w};
#pragma unroll
            for (int j = 0; j < 4; j++) {
                int s = q4 * 4 + j;
                float dA = __expf(dlt * Acoef[s]);
                h[s] = dA * h[s] + dx * bb[j];
                yv += h[s] * cc[j];
            }
        }
        const float sig = 1.f / (1.f + __expf(-zv));
        const float v = (yv + Dc * xcv) * (zv * sig);
        __nv_bfloat16 hh = __float2bfloat16(v);
        y_hi[(size_t)l * DD + c] = hh;
        y_lo[(size_t)l * DD + c] = __float2bfloat16(v - __bfloat162float(hh));
    }
}

// ---------------- zero output ----------------
__global__ void zero_kernel(float* __restrict__ p, int n4) {
    int idx = blockIdx.x * blockDim.x + threadIdx.x;
    if (idx < n4) ((float4*)p)[idx] = make_float4(0.f, 0.f, 0.f, 0.f);
}

// ---------------- host launcher ----------------
extern "C" void kernel_launch(void* const* d_in, const int* in_sizes, int n_in,
                              void* d_out, int out_size) {
    const float* q   = (const float*)d_in[0];
    const float* k_v = (const float*)d_in[1];
    const float* k_e = (const float*)d_in[2];
    const int*   index = (const int*)d_in[3];
    int base = (in_sizes[4] == 1) ? 5 : 4;
    const int*   edge_batch = (const int*)d_in[base + 0];
    const float* w_weight   = (const float*)d_in[base + 1];
    const float* w_bias     = (const float*)d_in[base + 2];
    const float* in_proj_w  = (const float*)d_in[base + 3];
    const float* conv_w     = (const float*)d_in[base + 4];
    const float* conv_b     = (const float*)d_in[base + 5];
    const float* x_proj_w   = (const float*)d_in[base + 6];
    const float* dt_proj_w  = (const float*)d_in[base + 7];
    const float* dt_proj_b  = (const float*)d_in[base + 8];
    const float* A_log      = (const float*)d_in[base + 9];
    const float* Dvec       = (const float*)d_in[base + 10];
    const float* out_proj_w = (const float*)d_in[base + 11];
    float* out = (float*)d_out;

    void *p;
    __nv_bfloat16 *cat_hi, *cat_lo, *x_hi, *x_lo, *y_hi, *y_lo;
    __nv_bfloat16 *wW_hi, *wW_lo, *wI_hi, *wI_lo, *wO_hi, *wO_lo;
    float *xz, *xc, *dbc, *delta;
    cudaGetSymbolAddress(&p, g_cat_hi); cat_hi = (__nv_bfloat16*)p;
    cudaGetSymbolAddress(&p, g_cat_lo); cat_lo = (__nv_bfloat16*)p;
    cudaGetSymbolAddress(&p, g_x_hi);   x_hi   = (__nv_bfloat16*)p;
    cudaGetSymbolAddress(&p, g_x_lo);   x_lo   = (__nv_bfloat16*)p;
    cudaGetSymbolAddress(&p, g_y_hi);   y_hi   = (__nv_bfloat16*)p;
    cudaGetSymbolAddress(&p, g_y_lo);   y_lo   = (__nv_bfloat16*)p;
    cudaGetSymbolAddress(&p, g_wW_hi);  wW_hi  = (__nv_bfloat16*)p;
    cudaGetSymbolAddress(&p, g_wW_lo);  wW_lo  = (__nv_bfloat16*)p;
    cudaGetSymbolAddress(&p, g_wI_hi);  wI_hi  = (__nv_bfloat16*)p;
    cudaGetSymbolAddress(&p, g_wI_lo);  wI_lo  = (__nv_bfloat16*)p;
    cudaGetSymbolAddress(&p, g_wO_hi);  wO_hi  = (__nv_bfloat16*)p;
    cudaGetSymbolAddress(&p, g_wO_lo);  wO_lo  = (__nv_bfloat16*)p;
    cudaGetSymbolAddress(&p, g_xz);     xz     = (float*)p;
    cudaGetSymbolAddress(&p, g_xc);     xc     = (float*)p;
    cudaGetSymbolAddress(&p, g_dbc);    dbc    = (float*)p;
    cudaGetSymbolAddress(&p, g_delta);  delta  = (float*)p;

    cudaFuncSetAttribute(tc_gemm_kernel<0>, cudaFuncAttributeMaxDynamicSharedMemorySize, TC_SMEM_BYTES);
    cudaFuncSetAttribute(tc_gemm_kernel<1>, cudaFuncAttributeMaxDynamicSharedMemorySize, TC_SMEM_BYTES);
    cudaFuncSetAttribute(tc_gemm_kernel<3>, cudaFuncAttributeMaxDynamicSharedMemorySize, TC_SMEM_BYTES);

    // 0. split weights to bf16 hi/lo
    split_kernel<<<(EE * 3 * EE + 255) / 256, 256>>>(w_weight,   wW_hi, wW_lo, EE * 3 * EE);
    split_kernel<<<(2 * DD * EE + 255) / 256, 256>>>(in_proj_w,  wI_hi, wI_lo, 2 * DD * EE);
    split_kernel<<<(EE * DD + 255) / 256, 256>>>(out_proj_w, wO_hi, wO_lo, EE * DD);

    // 1. concat(q, k_v, k_e) -> bf16 hi/lo [L, 1536]
    concat_split_kernel<<<(LL * 384 + 255) / 256, 256>>>(q, k_v, k_e, cat_hi, cat_lo);

    // 2. x = leakyrelu(cat @ w_weight^T + bias) -> bf16 hi/lo [L, 512]
    tc_gemm_kernel<1><<<dim3(EE / 128, LL / 128), 256, TC_SMEM_BYTES>>>(
        cat_hi, cat_lo, 3 * EE, wW_hi, wW_lo, w_bias,
        nullptr, 0, x_hi, x_lo, EE, nullptr, nullptr);

    // 3. xz = x @ in_proj_w^T -> fp32 [L, 1024]
    tc_gemm_kernel<0><<<dim3(2 * DD / 128, LL / 128), 256, TC_SMEM_BYTES>>>(
        x_hi, x_lo, EE, wI_hi, wI_lo, nullptr,
        xz, 2 * DD, nullptr, nullptr, 0, nullptr, nullptr);

    // 4. xc = silu(segmented_conv4(xz[:, :512]))
    conv_silu_kernel<<<(LL * 128 + 255) / 256, 256>>>(xz, edge_batch, conv_w, conv_b, xc);

    // 5. dbc = xc @ x_proj_w^T  [L, 64]  (SIMT, small)
    gemm_wt_kernel<128, 64, 16, 8, 4, 0><<<dim3(1, LL / 128), 256>>>(
        xc, DD, x_proj_w, nullptr, dbc, 64, LL, 64, DD);

    // 6. delta = softplus(dbc[:, :32] @ dt_proj_w^T + dt_proj_b)  [L, 512]  (SIMT)
    gemm_wt_kernel<128, 64, 16, 8, 4, 2><<<dim3(DD / 64, LL / 128), 256>>>(
        dbc, 64, dt_proj_w, dt_proj_b, delta, DD, LL, DD, DTRANK);

    // 7. segment boundaries
    segstart_kernel<<<1, 32>>>(edge_batch);

    // 8. scan + D skip + z gating -> y bf16 hi/lo
    scan_kernel<<<dim3(NGRAPH, DD / 128), 128>>>(delta, dbc, xc, xz, A_log, Dvec, y_hi, y_lo);

    // 9. zero output
    zero_kernel<<<(out_size / 4 + 255) / 256, 256>>>(out, out_size / 4);

    // 10. out[node] += y @ out_proj_w^T  (fused atomic segment-sum)
    tc_gemm_kernel<3><<<dim3(EE / 128, LL / 128), 256, TC_SMEM_BYTES>>>(
        y_hi, y_lo, DD, wO_hi, wO_lo, nullptr,
        nullptr, EE, nullptr, nullptr, 0, index, out);
}

// round 7
// speedup vs baseline: 2.8038x; 1.6224x over previous
#include <cuda_runtime.h>
#include <cuda_bf16.h>
#include <math.h>
#include <stdint.h>

// ---------------- problem constants ----------------
#define LL      8192
#define EE      512
#define DD      512
#define DSTATE  16
#define DCONV   4
#define DTRANK  32
#define NGRAPH  16

// tcgen05 is an arch-accelerated feature: only legal in sm_103a/sm_100a passes.
#if defined(__CUDA_ARCH_FEAT_SM103_ALL) || defined(__CUDA_ARCH_FEAT_SM100_ALL) || defined(__CUDA_ARCH_FEAT_SM101_ALL)
#define HAS_TCGEN05 1
#else
#define HAS_TCGEN05 0
#endif

// ---------------- scratch (static, alloc-free) ----------------
__device__ __nv_bfloat16 g_cat_hi[(size_t)LL * 3 * EE];
__device__ __nv_bfloat16 g_cat_lo[(size_t)LL * 3 * EE];
__device__ __nv_bfloat16 g_x_hi  [(size_t)LL * EE];
__device__ __nv_bfloat16 g_x_lo  [(size_t)LL * EE];
__device__ __nv_bfloat16 g_y_hi  [(size_t)LL * DD];
__device__ __nv_bfloat16 g_y_lo  [(size_t)LL * DD];
__device__ __nv_bfloat16 g_wW_hi [(size_t)EE * 3 * EE];
__device__ __nv_bfloat16 g_wW_lo [(size_t)EE * 3 * EE];
__device__ __nv_bfloat16 g_wI_hi [(size_t)2 * DD * EE];
__device__ __nv_bfloat16 g_wI_lo [(size_t)2 * DD * EE];
__device__ __nv_bfloat16 g_wO_hi [(size_t)EE * DD];
__device__ __nv_bfloat16 g_wO_lo [(size_t)EE * DD];
__device__ float g_xz   [(size_t)LL * 2 * DD];
__device__ float g_xc   [(size_t)LL * DD];
__device__ float g_dbc  [(size_t)LL * 64];
__device__ float g_delta[(size_t)LL * DD];
__device__ int   g_segstart[NGRAPH + 1];

// ---------------- cp.async (sm_80+, legal in any pass) ----------------
#define CP_ASYNC16(dst, src) \
    asm volatile("cp.async.cg.shared.global [%0], [%1], 16;" \
                 :: "r"((uint32_t)(dst)), "l"(src) : "memory")
#define CP_COMMIT() asm volatile("cp.async.commit_group;" ::: "memory")
#define CP_WAIT0()  asm volatile("cp.async.wait_group 0;" ::: "memory")

// ================= PTX helpers (guarded; sm_103a tcgen05) =================
#if HAS_TCGEN05
__device__ __forceinline__ uint32_t smem_u32(const void* p) {
    uint32_t a;
    asm("{ .reg .u64 t; cvta.to.shared.u64 t, %1; cvt.u32.u64 %0, t; }"
        : "=r"(a) : "l"(p));
    return a;
}
__device__ __forceinline__ uint32_t elect_one_pred() {
    uint32_t pred;
    asm volatile("{\n\t.reg .pred p;\n\telect.sync _|p, 0xFFFFFFFF;\n\t"
                 "selp.b32 %0, 1, 0, p;\n\t}" : "=r"(pred));
    return pred;
}
#define TCGEN05_ALLOC(sm_addr, nCols) \
    asm volatile("tcgen05.alloc.cta_group::1.sync.aligned.shared::cta.b32 [%0], %1;" \
                 :: "r"((uint32_t)(sm_addr)), "r"((uint32_t)(nCols)) : "memory")
#define TCGEN05_DEALLOC(tmem_addr, nCols) \
    asm volatile("tcgen05.dealloc.cta_group::1.sync.aligned.b32 %0, %1;" \
                 :: "r"(tmem_addr), "r"((uint32_t)(nCols)))
#define TCGEN05_RELINQ() \
    asm volatile("tcgen05.relinquish_alloc_permit.cta_group::1.sync.aligned;")
#define TCGEN05_COMMIT(mbar) \
    asm volatile("tcgen05.commit.cta_group::1.mbarrier::arrive::one.shared::cluster.b64 [%0];" \
                 :: "r"((uint32_t)(mbar)) : "memory")
#define TCGEN05_FENCE_AFTER() \
    asm volatile("tcgen05.fence::after_thread_sync;" ::: "memory")
#define TCGEN05_WAIT_LD() \
    asm volatile("tcgen05.wait::ld.sync.aligned;" ::: "memory")
#define FENCE_ASYNC_SHARED() \
    asm volatile("fence.proxy.async.shared::cta;" ::: "memory")
#define MBARRIER_INIT(mbar, cnt) \
    asm volatile("mbarrier.init.shared.b64 [%0], %1;" \
                 :: "r"((uint32_t)(mbar)), "r"((uint32_t)(cnt)) : "memory")
#define MBARRIER_WAIT_PARITY(mbar, parity) do { \
    uint32_t _mbar = (uint32_t)(mbar); \
    uint32_t _par  = (uint32_t)(parity); \
    uint32_t _done; \
    asm volatile("{\n\t.reg .pred p;\n\t" \
        "mbarrier.try_wait.parity.acquire.cta.shared::cta.b64 p, [%1], %2;\n\t" \
        "selp.b32 %0, 1, 0, p;\n\t}" : "=r"(_done) : "r"(_mbar), "r"(_par) : "memory"); \
    if (!_done) { \
        asm volatile("{\n\t.reg .pred P1;\n\t" \
            "WAIT_LOOP_%=:\n\t" \
            "mbarrier.try_wait.parity.acquire.cta.shared::cta.b64 P1, [%0], %1, 0x989680;\n\t" \
            "@P1 bra.uni WAIT_DONE_%=;\n\t" \
            "bra.uni WAIT_LOOP_%=;\n\t" \
            "WAIT_DONE_%=:\n\t}" :: "r"(_mbar), "r"(_par) : "memory"); \
    } \
} while (0)
#define TCGEN05_LD_32X32B_X32(r, tmem_addr) \
    asm volatile("tcgen05.ld.sync.aligned.32x32b.x32.b32 " \
        "{%0, %1, %2, %3, %4, %5, %6, %7, %8, %9, %10, %11, %12, %13, %14, %15, " \
        " %16, %17, %18, %19, %20, %21, %22, %23, %24, %25, %26, %27, %28, %29, %30, %31}, [%32];" \
        : "=r"((r)[0]),  "=r"((r)[1]),  "=r"((r)[2]),  "=r"((r)[3]), \
          "=r"((r)[4]),  "=r"((r)[5]),  "=r"((r)[6]),  "=r"((r)[7]), \
          "=r"((r)[8]),  "=r"((r)[9]),  "=r"((r)[10]), "=r"((r)[11]), \
          "=r"((r)[12]), "=r"((r)[13]), "=r"((r)[14]), "=r"((r)[15]), \
          "=r"((r)[16]), "=r"((r)[17]), "=r"((r)[18]), "=r"((r)[19]), \
          "=r"((r)[20]), "=r"((r)[21]), "=r"((r)[22]), "=r"((r)[23]), \
          "=r"((r)[24]), "=r"((r)[25]), "=r"((r)[26]), "=r"((r)[27]), \
          "=r"((r)[28]), "=r"((r)[29]), "=r"((r)[30]), "=r"((r)[31]) \
        : "r"(tmem_addr))

__device__ __forceinline__ void mma_bf16_ss(uint32_t d_tmem, uint64_t a_desc,
                                            uint64_t b_desc, uint32_t idesc,
                                            uint32_t acc) {
    asm volatile("{\n\t.reg .pred p;\n\tsetp.ne.u32 p, %4, 0;\n\t"
        "tcgen05.mma.cta_group::1.kind::f16 [%0], %1, %2, %3, {%5, %5, %5, %5}, p;\n\t}"
        :: "r"(d_tmem), "l"(a_desc), "l"(b_desc), "r"(idesc), "r"(acc), "r"(0u)
        : "memory");
}
__device__ __forceinline__ uint64_t make_desc_sw128(uint32_t addr) {
    const uint64_t BASE = (2ull << 61) | (1ull << 46) | (64ull << 32) | (1ull << 16);
    return BASE | ((uint64_t)(addr >> 4) & 0x3FFF);
}
#endif  // HAS_TCGEN05

#define SWZ(o) ((o) ^ (((o) >> 3) & 0x70))

// ================= split-bf16 GEMM (tcgen05 + cp.async pipeline) ============
// C[M=128/CTA, N=128/CTA] = (Ahi+Alo)[M,K] @ (Whi+Wlo)[N,K]^T  (lo*lo dropped)
// EPI: 0 = fp32 store | 1 = bias+leakyrelu -> bf16 hi/lo | 3 = atomic segsum
#define TC_SMEM_BYTES (1024 + 2 * 4 * 16384)

#if HAS_TCGEN05
// async-copy one 128x64 bf16 tile (16 KB, SW128-swizzled)
__device__ __forceinline__ void tc_cp_tile(uint32_t dst_sb, const __nv_bfloat16* src,
                                           int ld, int tid) {
#pragma unroll
    for (int t = 0; t < 4; t++) {
        int idx = tid + t * 256;          // 0..1023 16B vectors
        int r   = idx >> 3;
        int c16 = idx & 7;
        CP_ASYNC16(dst_sb + SWZ(r * 128 + c16 * 16),
                   src + (size_t)r * ld + c16 * 8);
    }
}
#endif

template <int EPI>
__global__ void __launch_bounds__(256, 1)
tc_gemm_kernel(const __nv_bfloat16* __restrict__ Ahi,
               const __nv_bfloat16* __restrict__ Alo, int K,
               const __nv_bfloat16* __restrict__ Whi,
               const __nv_bfloat16* __restrict__ Wlo,
               const float* __restrict__ bias,
               float* __restrict__ Cf, int ldc,
               __nv_bfloat16* __restrict__ Chi,
               __nv_bfloat16* __restrict__ Clo, int ldch,
               const int* __restrict__ index,
               float* __restrict__ segout) {
    extern __shared__ char smem[];
    const int tid = threadIdx.x;
    const int n0 = blockIdx.x * 128;
    const int m0 = blockIdx.y * 128;

#if HAS_TCGEN05
    // ======================= tcgen05 path =======================
    const int wid = tid >> 5;
    const int lid = tid & 31;
    const uint32_t sb = smem_u32(smem);

    if (wid == 0) TCGEN05_ALLOC(sb, 128);
    if (tid == 0) { MBARRIER_INIT(sb + 16, 1); MBARRIER_INIT(sb + 24, 1); }
    __syncthreads();
    uint32_t tmem;
    asm volatile("ld.shared.b32 %0, [%1];" : "=r"(tmem) : "r"(sb));

    const int NC = K >> 6;                 // 64-bf16 chunks
    const uint32_t idesc = (1u << 4) | (1u << 7) | (1u << 10) |
                           ((128u / 8) << 17) | ((128u / 16) << 24);

    const __nv_bfloat16* Ahi0 = Ahi + (size_t)m0 * K;
    const __nv_bfloat16* Alo0 = Alo + (size_t)m0 * K;
    const __nv_bfloat16* Whi0 = Whi + (size_t)n0 * K;
    const __nv_bfloat16* Wlo0 = Wlo + (size_t)n0 * K;

    // prologue: async-load chunk 0 into stage 0
    {
        const uint32_t base = sb + 1024;
        tc_cp_tile(base,          Ahi0, K, tid);
        tc_cp_tile(base + 16384,  Alo0, K, tid);
        tc_cp_tile(base + 32768,  Whi0, K, tid);
        tc_cp_tile(base + 49152,  Wlo0, K, tid);
        CP_COMMIT();
        CP_WAIT0();
        FENCE_ASYNC_SHARED();
    }
    __syncthreads();

    int ph0 = 0, ph1 = 0;
    for (int i = 0; i < NC; i++) {
        const int b = i & 1;
        // 1) issue chunk i's MMAs (data guaranteed by previous iteration's sync)
        if (wid == 0) {
            if (elect_one_pred()) {
                const uint32_t tb = sb + 1024 + b * 65536;
                const uint64_t dAh = make_desc_sw128(tb);
                const uint64_t dAl = make_desc_sw128(tb + 16384);
                const uint64_t dWh = make_desc_sw128(tb + 32768);
                const uint64_t dWl = make_desc_sw128(tb + 49152);
#pragma unroll
                for (int ks = 0; ks < 4; ks++)
                    mma_bf16_ss(tmem, dAh + ks * 2, dWh + ks * 2, idesc,
                                (i > 0 || ks > 0) ? 1u : 0u);
#pragma unroll
                for (int ks = 0; ks < 4; ks++)
                    mma_bf16_ss(tmem, dAh + ks * 2, dWl + ks * 2, idesc, 1u);
#pragma unroll
                for (int ks = 0; ks < 4; ks++)
                    mma_bf16_ss(tmem, dAl + ks * 2, dWh + ks * 2, idesc, 1u);
                TCGEN05_COMMIT(sb + 16 + b * 8);
            }
        }
        // 2) prefetch chunk i+1 into the other stage (overlaps chunk i's MMAs)
        if (i + 1 < NC) {
            const int b2 = b ^ 1;
            if (i >= 1) {   // stage b2 held chunk i-1; its MMAs committed already
                if (b2 == 0) { MBARRIER_WAIT_PARITY(sb + 16, ph0 & 1); ph0++; }
                else         { MBARRIER_WAIT_PARITY(sb + 24, ph1 & 1); ph1++; }
            }
            const int k0 = (i + 1) << 6;
            const uint32_t base = sb + 1024 + b2 * 65536;
            tc_cp_tile(base,          Ahi0 + k0, K, tid);
            tc_cp_tile(base + 16384,  Alo0 + k0, K, tid);
            tc_cp_tile(base + 32768,  Whi0 + k0, K, tid);
            tc_cp_tile(base + 49152,  Wlo0 + k0, K, tid);
            CP_COMMIT();
            CP_WAIT0();
            FENCE_ASYNC_SHARED();
            __syncthreads();
        }
    }
    if (((NC - 1) & 1) == 0) { MBARRIER_WAIT_PARITY(sb + 16, ph0 & 1); }
    else                     { MBARRIER_WAIT_PARITY(sb + 24, ph1 & 1); }
    TCGEN05_FENCE_AFTER();

    if (wid < 4) {
        const int m = m0 + wid * 32 + lid;
        int node = 0;
        if (EPI == 3) node = index[m];
#pragma unroll
        for (int cb = 0; cb < 4; cb++) {
            uint32_t dr[32];
            TCGEN05_LD_32X32B_X32(dr, tmem + cb * 32);
            TCGEN05_WAIT_LD();
            const int nb = n0 + cb * 32;
            if (EPI == 0) {
                float4* dst = (float4*)(Cf + (size_t)m * ldc + nb);
#pragma unroll
                for (int j4 = 0; j4 < 8; j4++)
                    dst[j4] = make_float4(__uint_as_float(dr[j4 * 4 + 0]),
                                          __uint_as_float(dr[j4 * 4 + 1]),
                                          __uint_as_float(dr[j4 * 4 + 2]),
                                          __uint_as_float(dr[j4 * 4 + 3]));
            } else if (EPI == 1) {
                __nv_bfloat162 hi[16], lo[16];
#pragma unroll
                for (int j2 = 0; j2 < 16; j2++) {
                    float a = __uint_as_float(dr[j2 * 2 + 0]) + bias[nb + j2 * 2 + 0];
                    float b = __uint_as_float(dr[j2 * 2 + 1]) + bias[nb + j2 * 2 + 1];
                    a = (a >= 0.f) ? a : 0.01f * a;
                    b = (b >= 0.f) ? b : 0.01f * b;
                    __nv_bfloat162 h = __floats2bfloat162_rn(a, b);
                    hi[j2] = h;
                    lo[j2] = __floats2bfloat162_rn(a - __bfloat162float(h.x),
                                                   b - __bfloat162float(h.y));
                }
                uint4* dh = (uint4*)(Chi + (size_t)m * ldch + nb);
                uint4* dl = (uint4*)(Clo + (size_t)m * ldch + nb);
#pragma unroll
                for (int j4 = 0; j4 < 4; j4++) {
                    dh[j4] = ((uint4*)hi)[j4];
                    dl[j4] = ((uint4*)lo)[j4];
                }
            } else {
                float* dst = segout + (size_t)node * ldc + nb;
#pragma unroll
                for (int j = 0; j < 32; j++)
                    atomicAdd(dst + j, __uint_as_float(dr[j]));
            }
        }
    }
    __syncthreads();
    if (wid == 0) {
        TCGEN05_RELINQ();
        TCGEN05_DEALLOC(tmem, 128);
    }
#else
    // ======================= SIMT fallback (non-'a' pass) =======================
    float* As = (float*)smem;           // [16][128]
    float* Bs = As + 16 * 128;          // [16][128]
    const int tx = tid & 15;
    const int ty = tid >> 4;

    float acc[8][8];
#pragma unroll
    for (int i = 0; i < 8; i++)
#pragma unroll
        for (int j = 0; j < 8; j++) acc[i][j] = 0.f;

    const __nv_bfloat16* Ahi0 = Ahi + (size_t)m0 * K;
    const __nv_bfloat16* Alo0 = Alo + (size_t)m0 * K;
    const __nv_bfloat16* Whi0 = Whi + (size_t)n0 * K;
    const __nv_bfloat16* Wlo0 = Wlo + (size_t)n0 * K;

    const int lrow = tid >> 1;
    const int lkc  = (tid & 1) * 8;

    for (int k0 = 0; k0 < K; k0 += 16) {
        {
            uint4 vh = *(const uint4*)(Ahi0 + (size_t)lrow * K + k0 + lkc);
            uint4 vl = *(const uint4*)(Alo0 + (size_t)lrow * K + k0 + lkc);
            const __nv_bfloat16* hh = (const __nv_bfloat16*)&vh;
            const __nv_bfloat16* ll = (const __nv_bfloat16*)&vl;
#pragma unroll
            for (int j = 0; j < 8; j++)
                As[(lkc + j) * 128 + lrow] =
                    __bfloat162float(hh[j]) + __bfloat162float(ll[j]);
        }
        {
            uint4 vh = *(const uint4*)(Whi0 + (size_t)lrow * K + k0 + lkc);
            uint4 vl = *(const uint4*)(Wlo0 + (size_t)lrow * K + k0 + lkc);
            const __nv_bfloat16* hh = (const __nv_bfloat16*)&vh;
            const __nv_bfloat16* ll = (const __nv_bfloat16*)&vl;
#pragma unroll
            for (int j = 0; j < 8; j++)
                Bs[(lkc + j) * 128 + lrow] =
                    __bfloat162float(hh[j]) + __bfloat162float(ll[j]);
        }
        __syncthreads();
#pragma unroll
        for (int k = 0; k < 16; k++) {
            float a[8], b[8];
#pragma unroll
            for (int i = 0; i < 8; i++) a[i] = As[k * 128 + ty * 8 + i];
#pragma unroll
            for (int j = 0; j < 8; j++) b[j] = Bs[k * 128 + tx * 8 + j];
#pragma unroll
            for (int i = 0; i < 8; i++)
#pragma unroll
                for (int j = 0; j < 8; j++) acc[i][j] += a[i] * b[j];
        }
        __syncthreads();
    }

#pragma unroll
    for (int i = 0; i < 8; i++) {
        const int m = m0 + ty * 8 + i;
        int node = 0;
        if (EPI == 3) node = index[m];
#pragma unroll
        for (int j = 0; j < 8; j++) {
            const int n = n0 + tx * 8 + j;
            float v = acc[i][j];
            if (EPI == 1) {
                v += bias[n];
                v = (v >= 0.f) ? v : 0.01f * v;
                __nv_bfloat16 h = __float2bfloat16(v);
                Chi[(size_t)m * ldch + n] = h;
                Clo[(size_t)m * ldch + n] = __float2bfloat16(v - __bfloat162float(h));
            } else if (EPI == 3) {
                atomicAdd(segout + (size_t)node * ldc + n, v);
            } else {
                Cf[(size_t)m * ldc + n] = v;
            }
        }
    }
#endif
}

// ---------------- split fp32 -> bf16 hi/lo ----------------
__global__ void split_kernel(const float* __restrict__ w,
                             __nv_bfloat16* __restrict__ hi,
                             __nv_bfloat16* __restrict__ lo, int n) {
    int i = blockIdx.x * blockDim.x + threadIdx.x;
    if (i >= n) return;
    float v = w[i];
    __nv_bfloat16 h = __float2bfloat16(v);
    hi[i] = h;
    lo[i] = __float2bfloat16(v - __bfloat162float(h));
}

// ---------------- concat(q, k_v, k_e) + split ----------------
__global__ void concat_split_kernel(const float* __restrict__ q,
                                    const float* __restrict__ kv,
                                    const float* __restrict__ ke,
                                    __nv_bfloat16* __restrict__ hi,
                                    __nv_bfloat16* __restrict__ lo) {
    int idx = blockIdx.x * blockDim.x + threadIdx.x;   // L*384 float4
    if (idx >= LL * 384) return;
    int l  = idx / 384;
    int j4 = idx % 384;
    float4 v;
    if (j4 < 128)       v = ((const float4*)q )[(size_t)l * 128 + j4];
    else if (j4 < 256)  v = ((const float4*)kv)[(size_t)l * 128 + (j4 - 128)];
    else                v = ((const float4*)ke)[(size_t)l * 128 + (j4 - 256)];
    __nv_bfloat162 h0 = __floats2bfloat162_rn(v.x, v.y);
    __nv_bfloat162 h1 = __floats2bfloat162_rn(v.z, v.w);
    __nv_bfloat162 l0 = __floats2bfloat162_rn(v.x - __bfloat162float(h0.x),
                                              v.y - __bfloat162float(h0.y));
    __nv_bfloat162 l1 = __floats2bfloat162_rn(v.z - __bfloat162float(h1.x),
                                              v.w - __bfloat162float(h1.y));
    ((__nv_bfloat162*)hi)[idx * 2 + 0] = h0;
    ((__nv_bfloat162*)hi)[idx * 2 + 1] = h1;
    ((__nv_bfloat162*)lo)[idx * 2 + 0] = l0;
    ((__nv_bfloat162*)lo)[idx * 2 + 1] = l1;
}

// ---------------- SIMT GEMM (small GEMMs): C = epi(A[M,K] @ W[N,K]^T) -------
template <int BM, int BN, int BK, int TM, int TN, int EPI>
__global__ void __launch_bounds__((BM / TM) * (BN / TN))
gemm_wt_kernel(const float* __restrict__ A, int lda,
               const float* __restrict__ W,
               const float* __restrict__ bias,
               float* __restrict__ C, int ldc,
               int M, int N, int K) {
    constexpr int THREADS = (BM / TM) * (BN / TN);
    constexpr int LA = BM * BK / (4 * THREADS);
    constexpr int LB = BN * BK / (4 * THREADS);
    __shared__ float As[BK][BM];
    __shared__ float Bs[BK][BN];

    const int tid = threadIdx.x;
    const int m0 = blockIdx.y * BM;
    const int n0 = blockIdx.x * BN;
    const int tx = tid % (BN / TN);
    const int ty = tid / (BN / TN);

    float acc[TM][TN];
#pragma unroll
    for (int i = 0; i < TM; i++)
#pragma unroll
        for (int j = 0; j < TN; j++) acc[i][j] = 0.f;

    for (int k0 = 0; k0 < K; k0 += BK) {
#pragma unroll
        for (int i = 0; i < LA; i++) {
            int idx = tid + i * THREADS;
            int row = idx / (BK / 4);
            int kc  = (idx % (BK / 4)) * 4;
            float4 v = *(const float4*)(A + (size_t)(m0 + row) * lda + k0 + kc);
            As[kc + 0][row] = v.x; As[kc + 1][row] = v.y;
            As[kc + 2][row] = v.z; As[kc + 3][row] = v.w;
        }
#pragma unroll
        for (int i = 0; i < LB; i++) {
            int idx = tid + i * THREADS;
            int row = idx / (BK / 4);
            int kc  = (idx % (BK / 4)) * 4;
            float4 v = *(const float4*)(W + (size_t)(n0 + row) * K + k0 + kc);
            Bs[kc + 0][row] = v.x; Bs[kc + 1][row] = v.y;
            Bs[kc + 2][row] = v.z; Bs[kc + 3][row] = v.w;
        }
        __syncthreads();
#pragma unroll
        for (int k = 0; k < BK; k++) {
            float a[TM], b[TN];
#pragma unroll
            for (int i = 0; i < TM; i++) a[i] = As[k][ty * TM + i];
#pragma unroll
            for (int j = 0; j < TN; j++) b[j] = Bs[k][tx * TN + j];
#pragma unroll
            for (int i = 0; i < TM; i++)
#pragma unroll
                for (int j = 0; j < TN; j++) acc[i][j] += a[i] * b[j];
        }
        __syncthreads();
    }

#pragma unroll
    for (int i = 0; i < TM; i++) {
        const int m = m0 + ty * TM + i;
#pragma unroll
        for (int j = 0; j < TN; j++) {
            const int n = n0 + tx * TN + j;
            float v = acc[i][j];
            if (EPI == 2) {
                v += bias[n];
                v = (v > 20.f) ? v : log1pf(__expf(v));
            }
            C[(size_t)m * ldc + n] = v;
        }
    }
}

// ---------------- segmented causal conv (DCONV=4) + SiLU, float4 ------------
__global__ void conv_silu_kernel(const float* __restrict__ xz,   // [L, 2D]
                                 const int*   __restrict__ eb,
                                 const float* __restrict__ conv_w, // [D, 4]
                                 const float* __restrict__ conv_b,
                                 float* __restrict__ xc) {
    int idx = blockIdx.x * blockDim.x + threadIdx.x;  // L * 128 float4
    if (idx >= LL * 128) return;
    int l  = idx >> 7;
    int c4 = idx & 127;
    int ebl = eb[l];
    float4 acc = ((const float4*)conv_b)[c4];
    float4 w0 = ((const float4*)conv_w)[c4 * 4 + 0];
    float4 w1 = ((const float4*)conv_w)[c4 * 4 + 1];
    float4 w2 = ((const float4*)conv_w)[c4 * 4 + 2];
    float4 w3 = ((const float4*)conv_w)[c4 * 4 + 3];
    const float* wp0 = (const float*)&w0;
    const float* wp1 = (const float*)&w1;
    const float* wp2 = (const float*)&w2;
    const float* wp3 = (const float*)&w3;
#pragma unroll
    for (int k = 0; k < DCONV; k++) {
        int ls = l + k - (DCONV - 1);
        if (ls >= 0 && eb[ls] == ebl) {
            float4 xv = ((const float4*)xz)[(size_t)ls * 256 + c4];
            acc.x += wp0[k] * xv.x;
            acc.y += wp1[k] * xv.y;
            acc.z += wp2[k] * xv.z;
            acc.w += wp3[k] * xv.w;
        }
    }
    acc.x *= 1.f / (1.f + __expf(-acc.x));
    acc.y *= 1.f / (1.f + __expf(-acc.y));
    acc.z *= 1.f / (1.f + __expf(-acc.z));
    acc.w *= 1.f / (1.f + __expf(-acc.w));
    ((float4*)xc)[idx] = acc;
}

// ---------------- segment boundaries ----------------
__global__ void segstart_kernel(const int* __restrict__ eb) {
    int g = threadIdx.x;
    if (g > NGRAPH) return;
    int lo = 0, hi = LL;
    while (lo < hi) {
        int mid = (lo + hi) >> 1;
        if (eb[mid] < g) lo = mid + 1; else hi = mid;
    }
    g_segstart[g] = lo;
}

// ---------------- segmented selective scan + gating -> bf16 hi/lo -----------
// Fast path: if A_log rows are log(1..16) (the reference's structure),
// dA[s] = p^(s+1) with p = exp(-delta): 1 MUFU instead of 16 per step.
__global__ void scan_kernel(const float* __restrict__ delta,
                            const float* __restrict__ dbc,
                            const float* __restrict__ xc,
                            const float* __restrict__ xz,
                            const float* __restrict__ A_log,
                            const float* __restrict__ Dvec,
                            __nv_bfloat16* __restrict__ y_hi,
                            __nv_bfloat16* __restrict__ y_lo) {
    const int c = blockIdx.y * blockDim.x + threadIdx.x;
    const int g = blockIdx.x;
    const int s0 = g_segstart[g];
    const int s1 = g_segstart[g + 1];
    if (s0 >= s1) return;

    float Acoef[DSTATE];
    bool fast = true;
#pragma unroll
    for (int s = 0; s < DSTATE; s++) {
        Acoef[s] = -__expf(A_log[c * DSTATE + s]);
        fast = fast && (fabsf(Acoef[s] + (float)(s + 1)) <= 1e-4f * (float)(s + 1));
    }
    const float Dc = Dvec[c];

    float h[DSTATE];
#pragma unroll
    for (int s = 0; s < DSTATE; s++) h[s] = 0.f;

    // prefetch step s0
    float dlt = delta[(size_t)s0 * DD + c];
    float xcv = xc[(size_t)s0 * DD + c];
    float zv  = xz[(size_t)s0 * (2 * DD) + DD + c];
    float4 bc[8];
#pragma unroll
    for (int q4 = 0; q4 < 8; q4++)
        bc[q4] = __ldg((const float4*)(dbc + (size_t)s0 * 64 + DTRANK) + q4);

    for (int l = s0; l < s1; l++) {
        // prefetch step l+1 (independent of this step's compute)
        float n_dlt = 0.f, n_xcv = 0.f, n_zv = 0.f;
        float4 n_bc[8];
        if (l + 1 < s1) {
            n_dlt = delta[(size_t)(l + 1) * DD + c];
            n_xcv = xc[(size_t)(l + 1) * DD + c];
            n_zv  = xz[(size_t)(l + 1) * (2 * DD) + DD + c];
#pragma unroll
            for (int q4 = 0; q4 < 8; q4++)
                n_bc[q4] = __ldg((const float4*)(dbc + (size_t)(l + 1) * 64 + DTRANK) + q4);
        }

        float dA[DSTATE];
        if (fast) {
            const float p = __expf(-dlt);
            float pw = p;
#pragma unroll
            for (int s = 0; s < DSTATE; s++) { dA[s] = pw; pw *= p; }
        } else {
#pragma unroll
            for (int s = 0; s < DSTATE; s++) dA[s] = __expf(dlt * Acoef[s]);
        }

        const float dx = dlt * xcv;
        float yv = 0.f;
#pragma unroll
        for (int q4 = 0; q4 < 4; q4++) {
            const float* bb = (const float*)&bc[q4];
            const float* cc = (const float*)&bc[4 + q4];
#pragma unroll
            for (int j = 0; j < 4; j++) {
                int s = q4 * 4 + j;
                h[s] = dA[s] * h[s] + dx * bb[j];
                yv += h[s] * cc[j];
            }
        }
        const float sig = 1.f / (1.f + __expf(-zv));
        const float v = (yv + Dc * xcv) * (zv * sig);
        __nv_bfloat16 hh = __float2bfloat16(v);
        y_hi[(size_t)l * DD + c] = hh;
        y_lo[(size_t)l * DD + c] = __float2bfloat16(v - __bfloat162float(hh));

        dlt = n_dlt; xcv = n_xcv; zv = n_zv;
#pragma unroll
        for (int q4 = 0; q4 < 8; q4++) bc[q4] = n_bc[q4];
    }
}

// ---------------- zero output ----------------
__global__ void zero_kernel(float* __restrict__ p, int n4) {
    int idx = blockIdx.x * blockDim.x + threadIdx.x;
    if (idx < n4) ((float4*)p)[idx] = make_float4(0.f, 0.f, 0.f, 0.f);
}

// ---------------- host launcher ----------------
extern "C" void kernel_launch(void* const* d_in, const int* in_sizes, int n_in,
                              void* d_out, int out_size) {
    const float* q   = (const float*)d_in[0];
    const float* k_v = (const float*)d_in[1];
    const float* k_e = (const float*)d_in[2];
    const int*   index = (const int*)d_in[3];
    int base = (in_sizes[4] == 1) ? 5 : 4;
    const int*   edge_batch = (const int*)d_in[base + 0];
    const float* w_weight   = (const float*)d_in[base + 1];
    const float* w_bias     = (const float*)d_in[base + 2];
    const float* in_proj_w  = (const float*)d_in[base + 3];
    const float* conv_w     = (const float*)d_in[base + 4];
    const float* conv_b     = (const float*)d_in[base + 5];
    const float* x_proj_w   = (const float*)d_in[base + 6];
    const float* dt_proj_w  = (const float*)d_in[base + 7];
    const float* dt_proj_b  = (const float*)d_in[base + 8];
    const float* A_log      = (const float*)d_in[base + 9];
    const float* Dvec       = (const float*)d_in[base + 10];
    const float* out_proj_w = (const float*)d_in[base + 11];
    float* out = (float*)d_out;

    void *p;
    __nv_bfloat16 *cat_hi, *cat_lo, *x_hi, *x_lo, *y_hi, *y_lo;
    __nv_bfloat16 *wW_hi, *wW_lo, *wI_hi, *wI_lo, *wO_hi, *wO_lo;
    float *xz, *xc, *dbc, *delta;
    cudaGetSymbolAddress(&p, g_cat_hi); cat_hi = (__nv_bfloat16*)p;
    cudaGetSymbolAddress(&p, g_cat_lo); cat_lo = (__nv_bfloat16*)p;
    cudaGetSymbolAddress(&p, g_x_hi);   x_hi   = (__nv_bfloat16*)p;
    cudaGetSymbolAddress(&p, g_x_lo);   x_lo   = (__nv_bfloat16*)p;
    cudaGetSymbolAddress(&p, g_y_hi);   y_hi   = (__nv_bfloat16*)p;
    cudaGetSymbolAddress(&p, g_y_lo);   y_lo   = (__nv_bfloat16*)p;
    cudaGetSymbolAddress(&p, g_wW_hi);  wW_hi  = (__nv_bfloat16*)p;
    cudaGetSymbolAddress(&p, g_wW_lo);  wW_lo  = (__nv_bfloat16*)p;
    cudaGetSymbolAddress(&p, g_wI_hi);  wI_hi  = (__nv_bfloat16*)p;
    cudaGetSymbolAddress(&p, g_wI_lo);  wI_lo  = (__nv_bfloat16*)p;
    cudaGetSymbolAddress(&p, g_wO_hi);  wO_hi  = (__nv_bfloat16*)p;
    cudaGetSymbolAddress(&p, g_wO_lo);  wO_lo  = (__nv_bfloat16*)p;
    cudaGetSymbolAddress(&p, g_xz);     xz     = (float*)p;
    cudaGetSymbolAddress(&p, g_xc);     xc     = (float*)p;
    cudaGetSymbolAddress(&p, g_dbc);    dbc    = (float*)p;
    cudaGetSymbolAddress(&p, g_delta);  delta  = (float*)p;

    cudaFuncSetAttribute(tc_gemm_kernel<0>, cudaFuncAttributeMaxDynamicSharedMemorySize, TC_SMEM_BYTES);
    cudaFuncSetAttribute(tc_gemm_kernel<1>, cudaFuncAttributeMaxDynamicSharedMemorySize, TC_SMEM_BYTES);
    cudaFuncSetAttribute(tc_gemm_kernel<3>, cudaFuncAttributeMaxDynamicSharedMemorySize, TC_SMEM_BYTES);

    // 0. split weights to bf16 hi/lo
    split_kernel<<<(EE * 3 * EE + 255) / 256, 256>>>(w_weight,   wW_hi, wW_lo, EE * 3 * EE);
    split_kernel<<<(2 * DD * EE + 255) / 256, 256>>>(in_proj_w,  wI_hi, wI_lo, 2 * DD * EE);
    split_kernel<<<(EE * DD + 255) / 256, 256>>>(out_proj_w, wO_hi, wO_lo, EE * DD);

    // 1. concat(q, k_v, k_e) -> bf16 hi/lo [L, 1536]
    concat_split_kernel<<<(LL * 384 + 255) / 256, 256>>>(q, k_v, k_e, cat_hi, cat_lo);

    // 2. x = leakyrelu(cat @ w_weight^T + bias) -> bf16 hi/lo [L, 512]
    tc_gemm_kernel<1><<<dim3(EE / 128, LL / 128), 256, TC_SMEM_BYTES>>>(
        cat_hi, cat_lo, 3 * EE, wW_hi, wW_lo, w_bias,
        nullptr, 0, x_hi, x_lo, EE, nullptr, nullptr);

    // 3. xz = x @ in_proj_w^T -> fp32 [L, 1024]
    tc_gemm_kernel<0><<<dim3(2 * DD / 128, LL / 128), 256, TC_SMEM_BYTES>>>(
        x_hi, x_lo, EE, wI_hi, wI_lo, nullptr,
        xz, 2 * DD, nullptr, nullptr, 0, nullptr, nullptr);

    // 4. xc = silu(segmented_conv4(xz[:, :512]))
    conv_silu_kernel<<<(LL * 128 + 255) / 256, 256>>>(xz, edge_batch, conv_w, conv_b, xc);

    // 5. dbc = xc @ x_proj_w^T  [L, 64]  (SIMT, 64x64 tiles -> 128 CTAs)
    gemm_wt_kernel<64, 64, 16, 8, 4, 0><<<dim3(1, LL / 64), 128>>>(
        xc, DD, x_proj_w, nullptr, dbc, 64, LL, 64, DD);

    // 6. delta = softplus(dbc[:, :32] @ dt_proj_w^T + dt_proj_b)  [L, 512]
    gemm_wt_kernel<128, 64, 16, 8, 4, 2><<<dim3(DD / 64, LL / 128), 256>>>(
        dbc, 64, dt_proj_w, dt_proj_b, delta, DD, LL, DD, DTRANK);

    // 7. segment boundaries
    segstart_kernel<<<1, 32>>>(edge_batch);

    // 8. scan + D skip + z gating -> y bf16 hi/lo
    scan_kernel<<<dim3(NGRAPH, DD / 128), 128>>>(delta, dbc, xc, xz, A_log, Dvec, y_hi, y_lo);

    // 9. zero output
    zero_kernel<<<(out_size / 4 + 255) / 256, 256>>>(out, out_size / 4);

    // 10. out[node] += y @ out_proj_w^T  (fused atomic segment-sum)
    tc_gemm_kernel<3><<<dim3(EE / 128, LL / 128), 256, TC_SMEM_BYTES>>>(
        y_hi, y_lo, DD, wO_hi, wO_lo, nullptr,
        nullptr, EE, nullptr, nullptr, 0, index, out);
}

// round 9
// speedup vs baseline: 2.8040x; 1.0001x over previous
#include <cuda_runtime.h>
#include <cuda_bf16.h>
#include <math.h>
#include <stdint.h>

// ---------------- problem constants ----------------
#define LL      8192
#define EE      512
#define DD      512
#define DSTATE  16
#define DCONV   4
#define DTRANK  32
#define NGRAPH  16

// tcgen05 is an arch-accelerated feature: only legal in sm_103a/sm_100a passes.
#if defined(__CUDA_ARCH_FEAT_SM103_ALL) || defined(__CUDA_ARCH_FEAT_SM100_ALL) || defined(__CUDA_ARCH_FEAT_SM101_ALL)
#define HAS_TCGEN05 1
#else
#define HAS_TCGEN05 0
#endif

// ---------------- scratch (static, alloc-free) ----------------
__device__ __nv_bfloat16 g_cat_hi[(size_t)LL * 3 * EE];
__device__ __nv_bfloat16 g_cat_lo[(size_t)LL * 3 * EE];
__device__ __nv_bfloat16 g_x_hi  [(size_t)LL * EE];
__device__ __nv_bfloat16 g_x_lo  [(size_t)LL * EE];
__device__ __nv_bfloat16 g_y_hi  [(size_t)LL * DD];
__device__ __nv_bfloat16 g_y_lo  [(size_t)LL * DD];
__device__ __nv_bfloat16 g_wW_hi [(size_t)EE * 3 * EE];
__device__ __nv_bfloat16 g_wW_lo [(size_t)EE * 3 * EE];
__device__ __nv_bfloat16 g_wI_hi [(size_t)2 * DD * EE];
__device__ __nv_bfloat16 g_wI_lo [(size_t)2 * DD * EE];
__device__ __nv_bfloat16 g_wO_hi [(size_t)EE * DD];
__device__ __nv_bfloat16 g_wO_lo [(size_t)EE * DD];
__device__ float g_xz   [(size_t)LL * 2 * DD];
__device__ float g_xc   [(size_t)LL * DD];
__device__ float g_dbc  [(size_t)LL * 64];
__device__ float g_delta[(size_t)LL * DD];
__device__ int   g_segstart[NGRAPH + 1];

// ---------------- cp.async (sm_80+, legal in any pass) ----------------
#define CP_ASYNC16(dst, src) \
    asm volatile("cp.async.cg.shared.global [%0], [%1], 16;" \
                 :: "r"((uint32_t)(dst)), "l"(src) : "memory")
#define CP_COMMIT() asm volatile("cp.async.commit_group;" ::: "memory")
#define CP_WAIT0()  asm volatile("cp.async.wait_group 0;" ::: "memory")

// ================= PTX helpers (guarded; sm_103a tcgen05) =================
#if HAS_TCGEN05
__device__ __forceinline__ uint32_t smem_u32(const void* p) {
    uint32_t a;
    asm("{ .reg .u64 t; cvta.to.shared.u64 t, %1; cvt.u32.u64 %0, t; }"
        : "=r"(a) : "l"(p));
    return a;
}
__device__ __forceinline__ uint32_t elect_one_pred() {
    uint32_t pred;
    asm volatile("{\n\t.reg .pred p;\n\telect.sync _|p, 0xFFFFFFFF;\n\t"
                 "selp.b32 %0, 1, 0, p;\n\t}" : "=r"(pred));
    return pred;
}
#define TCGEN05_ALLOC(sm_addr, nCols) \
    asm volatile("tcgen05.alloc.cta_group::1.sync.aligned.shared::cta.b32 [%0], %1;" \
                 :: "r"((uint32_t)(sm_addr)), "r"((uint32_t)(nCols)) : "memory")
#define TCGEN05_DEALLOC(tmem_addr, nCols) \
    asm volatile("tcgen05.dealloc.cta_group::1.sync.aligned.b32 %0, %1;" \
                 :: "r"(tmem_addr), "r"((uint32_t)(nCols)))
#define TCGEN05_RELINQ() \
    asm volatile("tcgen05.relinquish_alloc_permit.cta_group::1.sync.aligned;")
#define TCGEN05_COMMIT(mbar) \
    asm volatile("tcgen05.commit.cta_group::1.mbarrier::arrive::one.shared::cluster.b64 [%0];" \
                 :: "r"((uint32_t)(mbar)) : "memory")
#define TCGEN05_FENCE_AFTER() \
    asm volatile("tcgen05.fence::after_thread_sync;" ::: "memory")
#define TCGEN05_WAIT_LD() \
    asm volatile("tcgen05.wait::ld.sync.aligned;" ::: "memory")
#define FENCE_ASYNC_SHARED() \
    asm volatile("fence.proxy.async.shared::cta;" ::: "memory")
#define MBARRIER_INIT(mbar, cnt) \
    asm volatile("mbarrier.init.shared.b64 [%0], %1;" \
                 :: "r"((uint32_t)(mbar)), "r"((uint32_t)(cnt)) : "memory")
#define MBARRIER_WAIT_PARITY(mbar, parity) do { \
    uint32_t _mbar = (uint32_t)(mbar); \
    uint32_t _par  = (uint32_t)(parity); \
    uint32_t _done; \
    asm volatile("{\n\t.reg .pred p;\n\t" \
        "mbarrier.try_wait.parity.acquire.cta.shared::cta.b64 p, [%1], %2;\n\t" \
        "selp.b32 %0, 1, 0, p;\n\t}" : "=r"(_done) : "r"(_mbar), "r"(_par) : "memory"); \
    if (!_done) { \
        asm volatile("{\n\t.reg .pred P1;\n\t" \
            "WAIT_LOOP_%=:\n\t" \
            "mbarrier.try_wait.parity.acquire.cta.shared::cta.b64 P1, [%0], %1, 0x989680;\n\t" \
            "@P1 bra.uni WAIT_DONE_%=;\n\t" \
            "bra.uni WAIT_LOOP_%=;\n\t" \
            "WAIT_DONE_%=:\n\t}" :: "r"(_mbar), "r"(_par) : "memory"); \
    } \
} while (0)
#define TCGEN05_LD_32X32B_X32(r, tmem_addr) \
    asm volatile("tcgen05.ld.sync.aligned.32x32b.x32.b32 " \
        "{%0, %1, %2, %3, %4, %5, %6, %7, %8, %9, %10, %11, %12, %13, %14, %15, " \
        " %16, %17, %18, %19, %20, %21, %22, %23, %24, %25, %26, %27, %28, %29, %30, %31}, [%32];" \
        : "=r"((r)[0]),  "=r"((r)[1]),  "=r"((r)[2]),  "=r"((r)[3]), \
          "=r"((r)[4]),  "=r"((r)[5]),  "=r"((r)[6]),  "=r"((r)[7]), \
          "=r"((r)[8]),  "=r"((r)[9]),  "=r"((r)[10]), "=r"((r)[11]), \
          "=r"((r)[12]), "=r"((r)[13]), "=r"((r)[14]), "=r"((r)[15]), \
          "=r"((r)[16]), "=r"((r)[17]), "=r"((r)[18]), "=r"((r)[19]), \
          "=r"((r)[20]), "=r"((r)[21]), "=r"((r)[22]), "=r"((r)[23]), \
          "=r"((r)[24]), "=r"((r)[25]), "=r"((r)[26]), "=r"((r)[27]), \
          "=r"((r)[28]), "=r"((r)[29]), "=r"((r)[30]), "=r"((r)[31]) \
        : "r"(tmem_addr))

__device__ __forceinline__ void mma_bf16_ss(uint32_t d_tmem, uint64_t a_desc,
                                            uint64_t b_desc, uint32_t idesc,
                                            uint32_t acc) {
    asm volatile("{\n\t.reg .pred p;\n\tsetp.ne.u32 p, %4, 0;\n\t"
        "tcgen05.mma.cta_group::1.kind::f16 [%0], %1, %2, %3, {%5, %5, %5, %5}, p;\n\t}"
        :: "r"(d_tmem), "l"(a_desc), "l"(b_desc), "r"(idesc), "r"(acc), "r"(0u)
        : "memory");
}
__device__ __forceinline__ uint64_t make_desc_sw128(uint32_t addr) {
    const uint64_t BASE = (2ull << 61) | (1ull << 46) | (64ull << 32) | (1ull << 16);
    return BASE | ((uint64_t)(addr >> 4) & 0x3FFF);
}
#endif  // HAS_TCGEN05

#define SWZ(o) ((o) ^ (((o) >> 3) & 0x70))

// ================= split-bf16 GEMM (tcgen05 + cp.async pipeline) ============
// C[M=128/CTA, N=128/CTA] = (Ahi+Alo)[M,K] @ (Whi+Wlo)[N,K]^T  (lo*lo dropped)
// EPI: 0 = fp32 store | 1 = bias+leakyrelu -> bf16 hi/lo | 3 = atomic segsum
#define TC_SMEM_BYTES (1024 + 2 * 4 * 16384)

#if HAS_TCGEN05
// async-copy one 128x64 bf16 tile (16 KB, SW128-swizzled)
__device__ __forceinline__ void tc_cp_tile(uint32_t dst_sb, const __nv_bfloat16* src,
                                           int ld, int tid) {
#pragma unroll
    for (int t = 0; t < 4; t++) {
        int idx = tid + t * 256;          // 0..1023 16B vectors
        int r   = idx >> 3;
        int c16 = idx & 7;
        CP_ASYNC16(dst_sb + SWZ(r * 128 + c16 * 16),
                   src + (size_t)r * ld + c16 * 8);
    }
}
#endif

template <int EPI>
__global__ void __launch_bounds__(256, 1)
tc_gemm_kernel(const __nv_bfloat16* __restrict__ Ahi,
               const __nv_bfloat16* __restrict__ Alo, int K,
               const __nv_bfloat16* __restrict__ Whi,
               const __nv_bfloat16* __restrict__ Wlo,
               const float* __restrict__ bias,
               float* __restrict__ Cf, int ldc,
               __nv_bfloat16* __restrict__ Chi,
               __nv_bfloat16* __restrict__ Clo, int ldch,
               const int* __restrict__ index,
               float* __restrict__ segout) {
    extern __shared__ char smem[];
    const int tid = threadIdx.x;
    const int n0 = blockIdx.x * 128;
    const int m0 = blockIdx.y * 128;

#if HAS_TCGEN05
    // ======================= tcgen05 path =======================
    const int wid = tid >> 5;
    const int lid = tid & 31;
    const uint32_t sb = smem_u32(smem);

    if (wid == 0) TCGEN05_ALLOC(sb, 128);
    if (tid == 0) { MBARRIER_INIT(sb + 16, 1); MBARRIER_INIT(sb + 24, 1); }
    __syncthreads();
    uint32_t tmem;
    asm volatile("ld.shared.b32 %0, [%1];" : "=r"(tmem) : "r"(sb));

    const int NC = K >> 6;                 // 64-bf16 chunks
    const uint32_t idesc = (1u << 4) | (1u << 7) | (1u << 10) |
                           ((128u / 8) << 17) | ((128u / 16) << 24);

    const __nv_bfloat16* Ahi0 = Ahi + (size_t)m0 * K;
    const __nv_bfloat16* Alo0 = Alo + (size_t)m0 * K;
    const __nv_bfloat16* Whi0 = Whi + (size_t)n0 * K;
    const __nv_bfloat16* Wlo0 = Wlo + (size_t)n0 * K;

    // prologue: async-load chunk 0 into stage 0
    {
        const uint32_t base = sb + 1024;
        tc_cp_tile(base,          Ahi0, K, tid);
        tc_cp_tile(base + 16384,  Alo0, K, tid);
        tc_cp_tile(base + 32768,  Whi0, K, tid);
        tc_cp_tile(base + 49152,  Wlo0, K, tid);
        CP_COMMIT();
        CP_WAIT0();
        FENCE_ASYNC_SHARED();
    }
    __syncthreads();

    int ph0 = 0, ph1 = 0;
    for (int i = 0; i < NC; i++) {
        const int b = i & 1;
        // 1) issue chunk i's MMAs (data guaranteed by previous iteration's sync)
        if (wid == 0) {
            if (elect_one_pred()) {
                const uint32_t tb = sb + 1024 + b * 65536;
                const uint64_t dAh = make_desc_sw128(tb);
                const uint64_t dAl = make_desc_sw128(tb + 16384);
                const uint64_t dWh = make_desc_sw128(tb + 32768);
                const uint64_t dWl = make_desc_sw128(tb + 49152);
#pragma unroll
                for (int ks = 0; ks < 4; ks++)
                    mma_bf16_ss(tmem, dAh + ks * 2, dWh + ks * 2, idesc,
                                (i > 0 || ks > 0) ? 1u : 0u);
#pragma unroll
                for (int ks = 0; ks < 4; ks++)
                    mma_bf16_ss(tmem, dAh + ks * 2, dWl + ks * 2, idesc, 1u);
#pragma unroll
                for (int ks = 0; ks < 4; ks++)
                    mma_bf16_ss(tmem, dAl + ks * 2, dWh + ks * 2, idesc, 1u);
                TCGEN05_COMMIT(sb + 16 + b * 8);
            }
        }
        // 2) prefetch chunk i+1 into the other stage (overlaps chunk i's MMAs)
        if (i + 1 < NC) {
            const int b2 = b ^ 1;
            if (i >= 1) {   // stage b2 held chunk i-1; its MMAs committed already
                if (b2 == 0) { MBARRIER_WAIT_PARITY(sb + 16, ph0 & 1); ph0++; }
                else         { MBARRIER_WAIT_PARITY(sb + 24, ph1 & 1); ph1++; }
            }
            const int k0 = (i + 1) << 6;
            const uint32_t base = sb + 1024 + b2 * 65536;
            tc_cp_tile(base,          Ahi0 + k0, K, tid);
            tc_cp_tile(base + 16384,  Alo0 + k0, K, tid);
            tc_cp_tile(base + 32768,  Whi0 + k0, K, tid);
            tc_cp_tile(base + 49152,  Wlo0 + k0, K, tid);
            CP_COMMIT();
            CP_WAIT0();
            FENCE_ASYNC_SHARED();
            __syncthreads();
        }
    }
    if (((NC - 1) & 1) == 0) { MBARRIER_WAIT_PARITY(sb + 16, ph0 & 1); }
    else                     { MBARRIER_WAIT_PARITY(sb + 24, ph1 & 1); }
    TCGEN05_FENCE_AFTER();

    if (wid < 4) {
        const int m = m0 + wid * 32 + lid;
        int node = 0;
        if (EPI == 3) node = index[m];
#pragma unroll
        for (int cb = 0; cb < 4; cb++) {
            uint32_t dr[32];
            TCGEN05_LD_32X32B_X32(dr, tmem + cb * 32);
            TCGEN05_WAIT_LD();
            const int nb = n0 + cb * 32;
            if (EPI == 0) {
                float4* dst = (float4*)(Cf + (size_t)m * ldc + nb);
#pragma unroll
                for (int j4 = 0; j4 < 8; j4++)
                    dst[j4] = make_float4(__uint_as_float(dr[j4 * 4 + 0]),
                                          __uint_as_float(dr[j4 * 4 + 1]),
                                          __uint_as_float(dr[j4 * 4 + 2]),
                                          __uint_as_float(dr[j4 * 4 + 3]));
            } else if (EPI == 1) {
                __nv_bfloat162 hi[16], lo[16];
#pragma unroll
                for (int j2 = 0; j2 < 16; j2++) {
                    float a = __uint_as_float(dr[j2 * 2 + 0]) + bias[nb + j2 * 2 + 0];
                    float b = __uint_as_float(dr[j2 * 2 + 1]) + bias[nb + j2 * 2 + 1];
                    a = (a >= 0.f) ? a : 0.01f * a;
                    b = (b >= 0.f) ? b : 0.01f * b;
                    __nv_bfloat162 h = __floats2bfloat162_rn(a, b);
                    hi[j2] = h;
                    lo[j2] = __floats2bfloat162_rn(a - __bfloat162float(h.x),
                                                   b - __bfloat162float(h.y));
                }
                uint4* dh = (uint4*)(Chi + (size_t)m * ldch + nb);
                uint4* dl = (uint4*)(Clo + (size_t)m * ldch + nb);
#pragma unroll
                for (int j4 = 0; j4 < 4; j4++) {
                    dh[j4] = ((uint4*)hi)[j4];
                    dl[j4] = ((uint4*)lo)[j4];
                }
            } else {
                float* dst = segout + (size_t)node * ldc + nb;
#pragma unroll
                for (int j = 0; j < 32; j++)
                    atomicAdd(dst + j, __uint_as_float(dr[j]));
            }
        }
    }
    __syncthreads();
    if (wid == 0) {
        TCGEN05_RELINQ();
        TCGEN05_DEALLOC(tmem, 128);
    }
#else
    // ======================= SIMT fallback (non-'a' pass) =======================
    float* As = (float*)smem;           // [16][128]
    float* Bs = As + 16 * 128;          // [16][128]
    const int tx = tid & 15;
    const int ty = tid >> 4;

    float acc[8][8];
#pragma unroll
    for (int i = 0; i < 8; i++)
#pragma unroll
        for (int j = 0; j < 8; j++) acc[i][j] = 0.f;

    const __nv_bfloat16* Ahi0 = Ahi + (size_t)m0 * K;
    const __nv_bfloat16* Alo0 = Alo + (size_t)m0 * K;
    const __nv_bfloat16* Whi0 = Whi + (size_t)n0 * K;
    const __nv_bfloat16* Wlo0 = Wlo + (size_t)n0 * K;

    const int lrow = tid >> 1;
    const int lkc  = (tid & 1) * 8;

    for (int k0 = 0; k0 < K; k0 += 16) {
        {
            uint4 vh = *(const uint4*)(Ahi0 + (size_t)lrow * K + k0 + lkc);
            uint4 vl = *(const uint4*)(Alo0 + (size_t)lrow * K + k0 + lkc);
            const __nv_bfloat16* hh = (const __nv_bfloat16*)&vh;
            const __nv_bfloat16* ll = (const __nv_bfloat16*)&vl;
#pragma unroll
            for (int j = 0; j < 8; j++)
                As[(lkc + j) * 128 + lrow] =
                    __bfloat162float(hh[j]) + __bfloat162float(ll[j]);
        }
        {
            uint4 vh = *(const uint4*)(Whi0 + (size_t)lrow * K + k0 + lkc);
            uint4 vl = *(const uint4*)(Wlo0 + (size_t)lrow * K + k0 + lkc);
            const __nv_bfloat16* hh = (const __nv_bfloat16*)&vh;
            const __nv_bfloat16* ll = (const __nv_bfloat16*)&vl;
#pragma unroll
            for (int j = 0; j < 8; j++)
                Bs[(lkc + j) * 128 + lrow] =
                    __bfloat162float(hh[j]) + __bfloat162float(ll[j]);
        }
        __syncthreads();
#pragma unroll
        for (int k = 0; k < 16; k++) {
            float a[8], b[8];
#pragma unroll
            for (int i = 0; i < 8; i++) a[i] = As[k * 128 + ty * 8 + i];
#pragma unroll
            for (int j = 0; j < 8; j++) b[j] = Bs[k * 128 + tx * 8 + j];
#pragma unroll
            for (int i = 0; i < 8; i++)
#pragma unroll
                for (int j = 0; j < 8; j++) acc[i][j] += a[i] * b[j];
        }
        __syncthreads();
    }

#pragma unroll
    for (int i = 0; i < 8; i++) {
        const int m = m0 + ty * 8 + i;
        int node = 0;
        if (EPI == 3) node = index[m];
#pragma unroll
        for (int j = 0; j < 8; j++) {
            const int n = n0 + tx * 8 + j;
            float v = acc[i][j];
            if (EPI == 1) {
                v += bias[n];
                v = (v >= 0.f) ? v : 0.01f * v;
                __nv_bfloat16 h = __float2bfloat16(v);
                Chi[(size_t)m * ldch + n] = h;
                Clo[(size_t)m * ldch + n] = __float2bfloat16(v - __bfloat162float(h));
            } else if (EPI == 3) {
                atomicAdd(segout + (size_t)node * ldc + n, v);
            } else {
                Cf[(size_t)m * ldc + n] = v;
            }
        }
    }
#endif
}

// ---------------- split fp32 -> bf16 hi/lo ----------------
__global__ void split_kernel(const float* __restrict__ w,
                             __nv_bfloat16* __restrict__ hi,
                             __nv_bfloat16* __restrict__ lo, int n) {
    int i = blockIdx.x * blockDim.x + threadIdx.x;
    if (i >= n) return;
    float v = w[i];
    __nv_bfloat16 h = __float2bfloat16(v);
    hi[i] = h;
    lo[i] = __float2bfloat16(v - __bfloat162float(h));
}

// ---------------- concat(q, k_v, k_e) + split ----------------
__global__ void concat_split_kernel(const float* __restrict__ q,
                                    const float* __restrict__ kv,
                                    const float* __restrict__ ke,
                                    __nv_bfloat16* __restrict__ hi,
                                    __nv_bfloat16* __restrict__ lo) {
    int idx = blockIdx.x * blockDim.x + threadIdx.x;   // L*384 float4
    if (idx >= LL * 384) return;
    int l  = idx / 384;
    int j4 = idx % 384;
    float4 v;
    if (j4 < 128)       v = ((const float4*)q )[(size_t)l * 128 + j4];
    else if (j4 < 256)  v = ((const float4*)kv)[(size_t)l * 128 + (j4 - 128)];
    else                v = ((const float4*)ke)[(size_t)l * 128 + (j4 - 256)];
    __nv_bfloat162 h0 = __floats2bfloat162_rn(v.x, v.y);
    __nv_bfloat162 h1 = __floats2bfloat162_rn(v.z, v.w);
    __nv_bfloat162 l0 = __floats2bfloat162_rn(v.x - __bfloat162float(h0.x),
                                              v.y - __bfloat162float(h0.y));
    __nv_bfloat162 l1 = __floats2bfloat162_rn(v.z - __bfloat162float(h1.x),
                                              v.w - __bfloat162float(h1.y));
    ((__nv_bfloat162*)hi)[idx * 2 + 0] = h0;
    ((__nv_bfloat162*)hi)[idx * 2 + 1] = h1;
    ((__nv_bfloat162*)lo)[idx * 2 + 0] = l0;
    ((__nv_bfloat162*)lo)[idx * 2 + 1] = l1;
}

// ---------------- SIMT GEMM (small GEMMs): C = epi(A[M,K] @ W[N,K]^T) -------
template <int BM, int BN, int BK, int TM, int TN, int EPI>
__global__ void __launch_bounds__((BM / TM) * (BN / TN))
gemm_wt_kernel(const float* __restrict__ A, int lda,
               const float* __restrict__ W,
               const float* __restrict__ bias,
               float* __restrict__ C, int ldc,
               int M, int N, int K) {
    constexpr int THREADS = (BM / TM) * (BN / TN);
    constexpr int LA = BM * BK / (4 * THREADS);
    constexpr int LB = BN * BK / (4 * THREADS);
    __shared__ float As[BK][BM];
    __shared__ float Bs[BK][BN];

    const int tid = threadIdx.x;
    const int m0 = blockIdx.y * BM;
    const int n0 = blockIdx.x * BN;
    const int tx = tid % (BN / TN);
    const int ty = tid / (BN / TN);

    float acc[TM][TN];
#pragma unroll
    for (int i = 0; i < TM; i++)
#pragma unroll
        for (int j = 0; j < TN; j++) acc[i][j] = 0.f;

    for (int k0 = 0; k0 < K; k0 += BK) {
#pragma unroll
        for (int i = 0; i < LA; i++) {
            int idx = tid + i * THREADS;
            int row = idx / (BK / 4);
            int kc  = (idx % (BK / 4)) * 4;
            float4 v = *(const float4*)(A + (size_t)(m0 + row) * lda + k0 + kc);
            As[kc + 0][row] = v.x; As[kc + 1][row] = v.y;
            As[kc + 2][row] = v.z; As[kc + 3][row] = v.w;
        }
#pragma unroll
        for (int i = 0; i < LB; i++) {
            int idx = tid + i * THREADS;
            int row = idx / (BK / 4);
            int kc  = (idx % (BK / 4)) * 4;
            float4 v = *(const float4*)(W + (size_t)(n0 + row) * K + k0 + kc);
            Bs[kc + 0][row] = v.x; Bs[kc + 1][row] = v.y;
            Bs[kc + 2][row] = v.z; Bs[kc + 3][row] = v.w;
        }
        __syncthreads();
#pragma unroll
        for (int k = 0; k < BK; k++) {
            float a[TM], b[TN];
#pragma unroll
            for (int i = 0; i < TM; i++) a[i] = As[k][ty * TM + i];
#pragma unroll
            for (int j = 0; j < TN; j++) b[j] = Bs[k][tx * TN + j];
#pragma unroll
            for (int i = 0; i < TM; i++)
#pragma unroll
                for (int j = 0; j < TN; j++) acc[i][j] += a[i] * b[j];
        }
        __syncthreads();
    }

#pragma unroll
    for (int i = 0; i < TM; i++) {
        const int m = m0 + ty * TM + i;
#pragma unroll
        for (int j = 0; j < TN; j++) {
            const int n = n0 + tx * TN + j;
            float v = acc[i][j];
            if (EPI == 2) {
                v += bias[n];
                v = (v > 20.f) ? v : log1pf(__expf(v));
            }
            C[(size_t)m * ldc + n] = v;
        }
    }
}

// ---------------- segmented causal conv (DCONV=4) + SiLU, float4 ------------
__global__ void conv_silu_kernel(const float* __restrict__ xz,   // [L, 2D]
                                 const int*   __restrict__ eb,
                                 const float* __restrict__ conv_w, // [D, 4]
                                 const float* __restrict__ conv_b,
                                 float* __restrict__ xc) {
    int idx = blockIdx.x * blockDim.x + threadIdx.x;  // L * 128 float4
    if (idx >= LL * 128) return;
    int l  = idx >> 7;
    int c4 = idx & 127;
    int ebl = eb[l];
    float4 acc = ((const float4*)conv_b)[c4];
    float4 w0 = ((const float4*)conv_w)[c4 * 4 + 0];
    float4 w1 = ((const float4*)conv_w)[c4 * 4 + 1];
    float4 w2 = ((const float4*)conv_w)[c4 * 4 + 2];
    float4 w3 = ((const float4*)conv_w)[c4 * 4 + 3];
    const float* wp0 = (const float*)&w0;
    const float* wp1 = (const float*)&w1;
    const float* wp2 = (const float*)&w2;
    const float* wp3 = (const float*)&w3;
#pragma unroll
    for (int k = 0; k < DCONV; k++) {
        int ls = l + k - (DCONV - 1);
        if (ls >= 0 && eb[ls] == ebl) {
            float4 xv = ((const float4*)xz)[(size_t)ls * 256 + c4];
            acc.x += wp0[k] * xv.x;
            acc.y += wp1[k] * xv.y;
            acc.z += wp2[k] * xv.z;
            acc.w += wp3[k] * xv.w;
        }
    }
    acc.x *= 1.f / (1.f + __expf(-acc.x));
    acc.y *= 1.f / (1.f + __expf(-acc.y));
    acc.z *= 1.f / (1.f + __expf(-acc.z));
    acc.w *= 1.f / (1.f + __expf(-acc.w));
    ((float4*)xc)[idx] = acc;
}

// ---------------- segment boundaries ----------------
__global__ void segstart_kernel(const int* __restrict__ eb) {
    int g = threadIdx.x;
    if (g > NGRAPH) return;
    int lo = 0, hi = LL;
    while (lo < hi) {
        int mid = (lo + hi) >> 1;
        if (eb[mid] < g) lo = mid + 1; else hi = mid;
    }
    g_segstart[g] = lo;
}

// ---------------- segmented selective scan + gating -> bf16 hi/lo -----------
// Fast path: if A_log rows are log(1..16) (the reference's structure),
// dA[s] = p^(s+1) with p = exp(-delta): 1 MUFU instead of 16 per step.
__global__ void scan_kernel(const float* __restrict__ delta,
                            const float* __restrict__ dbc,
                            const float* __restrict__ xc,
                            const float* __restrict__ xz,
                            const float* __restrict__ A_log,
                            const float* __restrict__ Dvec,
                            __nv_bfloat16* __restrict__ y_hi,
                            __nv_bfloat16* __restrict__ y_lo) {
    const int c = blockIdx.y * blockDim.x + threadIdx.x;
    const int g = blockIdx.x;
    const int s0 = g_segstart[g];
    const int s1 = g_segstart[g + 1];
    if (s0 >= s1) return;

    float Acoef[DSTATE];
    bool fast = true;
#pragma unroll
    for (int s = 0; s < DSTATE; s++) {
        Acoef[s] = -__expf(A_log[c * DSTATE + s]);
        fast = fast && (fabsf(Acoef[s] + (float)(s + 1)) <= 1e-4f * (float)(s + 1));
    }
    const float Dc = Dvec[c];

    float h[DSTATE];
#pragma unroll
    for (int s = 0; s < DSTATE; s++) h[s] = 0.f;

    // prefetch step s0
    float dlt = delta[(size_t)s0 * DD + c];
    float xcv = xc[(size_t)s0 * DD + c];
    float zv  = xz[(size_t)s0 * (2 * DD) + DD + c];
    float4 bc[8];
#pragma unroll
    for (int q4 = 0; q4 < 8; q4++)
        bc[q4] = __ldg((const float4*)(dbc + (size_t)s0 * 64 + DTRANK) + q4);

    for (int l = s0; l < s1; l++) {
        // prefetch step l+1 (independent of this step's compute)
        float n_dlt = 0.f, n_xcv = 0.f, n_zv = 0.f;
        float4 n_bc[8];
        if (l + 1 < s1) {
            n_dlt = delta[(size_t)(l + 1) * DD + c];
            n_xcv = xc[(size_t)(l + 1) * DD + c];
            n_zv  = xz[(size_t)(l + 1) * (2 * DD) + DD + c];
#pragma unroll
            for (int q4 = 0; q4 < 8; q4++)
                n_bc[q4] = __ldg((const float4*)(dbc + (size_t)(l + 1) * 64 + DTRANK) + q4);
        }

        float dA[DSTATE];
        if (fast) {
            const float p = __expf(-dlt);
            float pw = p;
#pragma unroll
            for (int s = 0; s < DSTATE; s++) { dA[s] = pw; pw *= p; }
        } else {
#pragma unroll
            for (int s = 0; s < DSTATE; s++) dA[s] = __expf(dlt * Acoef[s]);
        }

        const float dx = dlt * xcv;
        float yv = 0.f;
#pragma unroll
        for (int q4 = 0; q4 < 4; q4++) {
            const float* bb = (const float*)&bc[q4];
            const float* cc = (const float*)&bc[4 + q4];
#pragma unroll
            for (int j = 0; j < 4; j++) {
                int s = q4 * 4 + j;
                h[s] = dA[s] * h[s] + dx * bb[j];
                yv += h[s] * cc[j];
            }
        }
        const float sig = 1.f / (1.f + __expf(-zv));
        const float v = (yv + Dc * xcv) * (zv * sig);
        __nv_bfloat16 hh = __float2bfloat16(v);
        y_hi[(size_t)l * DD + c] = hh;
        y_lo[(size_t)l * DD + c] = __float2bfloat16(v - __bfloat162float(hh));

        dlt = n_dlt; xcv = n_xcv; zv = n_zv;
#pragma unroll
        for (int q4 = 0; q4 < 8; q4++) bc[q4] = n_bc[q4];
    }
}

// ---------------- zero output ----------------
__global__ void zero_kernel(float* __restrict__ p, int n4) {
    int idx = blockIdx.x * blockDim.x + threadIdx.x;
    if (idx < n4) ((float4*)p)[idx] = make_float4(0.f, 0.f, 0.f, 0.f);
}

// ---------------- host launcher ----------------
extern "C" void kernel_launch(void* const* d_in, const int* in_sizes, int n_in,
                              void* d_out, int out_size) {
    const float* q   = (const float*)d_in[0];
    const float* k_v = (const float*)d_in[1];
    const float* k_e = (const float*)d_in[2];
    const int*   index = (const int*)d_in[3];
    int base = (in_sizes[4] == 1) ? 5 : 4;
    const int*   edge_batch = (const int*)d_in[base + 0];
    const float* w_weight   = (const float*)d_in[base + 1];
    const float* w_bias     = (const float*)d_in[base + 2];
    const float* in_proj_w  = (const float*)d_in[base + 3];
    const float* conv_w     = (const float*)d_in[base + 4];
    const float* conv_b     = (const float*)d_in[base + 5];
    const float* x_proj_w   = (const float*)d_in[base + 6];
    const float* dt_proj_w  = (const float*)d_in[base + 7];
    const float* dt_proj_b  = (const float*)d_in[base + 8];
    const float* A_log      = (const float*)d_in[base + 9];
    const float* Dvec       = (const float*)d_in[base + 10];
    const float* out_proj_w = (const float*)d_in[base + 11];
    float* out = (float*)d_out;

    void *p;
    __nv_bfloat16 *cat_hi, *cat_lo, *x_hi, *x_lo, *y_hi, *y_lo;
    __nv_bfloat16 *wW_hi, *wW_lo, *wI_hi, *wI_lo, *wO_hi, *wO_lo;
    float *xz, *xc, *dbc, *delta;
    cudaGetSymbolAddress(&p, g_cat_hi); cat_hi = (__nv_bfloat16*)p;
    cudaGetSymbolAddress(&p, g_cat_lo); cat_lo = (__nv_bfloat16*)p;
    cudaGetSymbolAddress(&p, g_x_hi);   x_hi   = (__nv_bfloat16*)p;
    cudaGetSymbolAddress(&p, g_x_lo);   x_lo   = (__nv_bfloat16*)p;
    cudaGetSymbolAddress(&p, g_y_hi);   y_hi   = (__nv_bfloat16*)p;
    cudaGetSymbolAddress(&p, g_y_lo);   y_lo   = (__nv_bfloat16*)p;
    cudaGetSymbolAddress(&p, g_wW_hi);  wW_hi  = (__nv_bfloat16*)p;
    cudaGetSymbolAddress(&p, g_wW_lo);  wW_lo  = (__nv_bfloat16*)p;
    cudaGetSymbolAddress(&p, g_wI_hi);  wI_hi  = (__nv_bfloat16*)p;
    cudaGetSymbolAddress(&p, g_wI_lo);  wI_lo  = (__nv_bfloat16*)p;
    cudaGetSymbolAddress(&p, g_wO_hi);  wO_hi  = (__nv_bfloat16*)p;
    cudaGetSymbolAddress(&p, g_wO_lo);  wO_lo  = (__nv_bfloat16*)p;
    cudaGetSymbolAddress(&p, g_xz);     xz     = (float*)p;
    cudaGetSymbolAddress(&p, g_xc);     xc     = (float*)p;
    cudaGetSymbolAddress(&p, g_dbc);    dbc    = (float*)p;
    cudaGetSymbolAddress(&p, g_delta);  delta  = (float*)p;

    cudaFuncSetAttribute(tc_gemm_kernel<0>, cudaFuncAttributeMaxDynamicSharedMemorySize, TC_SMEM_BYTES);
    cudaFuncSetAttribute(tc_gemm_kernel<1>, cudaFuncAttributeMaxDynamicSharedMemorySize, TC_SMEM_BYTES);
    cudaFuncSetAttribute(tc_gemm_kernel<3>, cudaFuncAttributeMaxDynamicSharedMemorySize, TC_SMEM_BYTES);

    // 0. split weights to bf16 hi/lo
    split_kernel<<<(EE * 3 * EE + 255) / 256, 256>>>(w_weight,   wW_hi, wW_lo, EE * 3 * EE);
    split_kernel<<<(2 * DD * EE + 255) / 256, 256>>>(in_proj_w,  wI_hi, wI_lo, 2 * DD * EE);
    split_kernel<<<(EE * DD + 255) / 256, 256>>>(out_proj_w, wO_hi, wO_lo, EE * DD);

    // 1. concat(q, k_v, k_e) -> bf16 hi/lo [L, 1536]
    concat_split_kernel<<<(LL * 384 + 255) / 256, 256>>>(q, k_v, k_e, cat_hi, cat_lo);

    // 2. x = leakyrelu(cat @ w_weight^T + bias) -> bf16 hi/lo [L, 512]
    tc_gemm_kernel<1><<<dim3(EE / 128, LL / 128), 256, TC_SMEM_BYTES>>>(
        cat_hi, cat_lo, 3 * EE, wW_hi, wW_lo, w_bias,
        nullptr, 0, x_hi, x_lo, EE, nullptr, nullptr);

    // 3. xz = x @ in_proj_w^T -> fp32 [L, 1024]
    tc_gemm_kernel<0><<<dim3(2 * DD / 128, LL / 128), 256, TC_SMEM_BYTES>>>(
        x_hi, x_lo, EE, wI_hi, wI_lo, nullptr,
        xz, 2 * DD, nullptr, nullptr, 0, nullptr, nullptr);

    // 4. xc = silu(segmented_conv4(xz[:, :512]))
    conv_silu_kernel<<<(LL * 128 + 255) / 256, 256>>>(xz, edge_batch, conv_w, conv_b, xc);

    // 5. dbc = xc @ x_proj_w^T  [L, 64]  (SIMT, 64x64 tiles -> 128 CTAs)
    gemm_wt_kernel<64, 64, 16, 8, 4, 0><<<dim3(1, LL / 64), 128>>>(
        xc, DD, x_proj_w, nullptr, dbc, 64, LL, 64, DD);

    // 6. delta = softplus(dbc[:, :32] @ dt_proj_w^T + dt_proj_b)  [L, 512]
    gemm_wt_kernel<128, 64, 16, 8, 4, 2><<<dim3(DD / 64, LL / 128), 256>>>(
        dbc, 64, dt_proj_w, dt_proj_b, delta, DD, LL, DD, DTRANK);

    // 7. segment boundaries
    segstart_kernel<<<1, 32>>>(edge_batch);

    // 8. scan + D skip + z gating -> y bf16 hi/lo
    scan_kernel<<<dim3(NGRAPH, DD / 128), 128>>>(delta, dbc, xc, xz, A_log, Dvec, y_hi, y_lo);

    // 9. zero output
    zero_kernel<<<(out_size / 4 + 255) / 256, 256>>>(out, out_size / 4);

    // 10. out[node] += y @ out_proj_w^T  (fused atomic segment-sum)
    tc_gemm_kernel<3><<<dim3(EE / 128, LL / 128), 256, TC_SMEM_BYTES>>>(
        y_hi, y_lo, DD, wO_hi, wO_lo, nullptr,
        nullptr, EE, nullptr, nullptr, 0, index, out);
}